// round 1
// baseline (speedup 1.0000x reference)
#include <cuda_runtime.h>
#include <cuda_bf16.h>

// ---------------------------------------------------------------------------
// DeformableConv3D  (B=1, CIN=COUT=32, D=32, H=W=64, KS=3, stride=1, pad=1)
//
// Pipeline (all fp32, packed f32x2 FMAs for 2x fp32 throughput on sm_103a):
//   1. transpose x (C,D,H,W) -> xt (D,H,W,C)  [channels-last, 128B per voxel]
//   2. reorg weights: wr[tap][cin][oc0..107] (off||mask), wcv[k][cin][oc0..31]
//   3. conv kernel: offset(81) + sigmoid(mask)(27) per voxel -> g_offmask
//   4. deform kernel: trilinear gather + mask + contraction with w -> out
// ---------------------------------------------------------------------------

#define DD 32
#define HH 64
#define WW 64
#define NVOX (DD*HH*WW)        // 131072
#define CIN 32
#define COUT 32
#define KK 27
#define OC108 108

// scratch (device globals; no allocations allowed)
__device__ float g_xt[NVOX * CIN];               // 16 MB channels-last x
__device__ float g_wr[KK * CIN * OC108];         // conv weights [tap][cin][oc]
__device__ float g_wcv[KK * CIN * COUT];         // deform weights [k][cin][oc]
__device__ float g_bias108[OC108];
__device__ float g_offmask[(size_t)NVOX * OC108];// 56.6 MB

// ---------------- packed f32x2 helpers --------------------------------------
__device__ __forceinline__ unsigned long long pack2(float a, float b) {
    unsigned long long r;
    asm("mov.b64 %0, {%1, %2};"
        : "=l"(r) : "r"(__float_as_uint(a)), "r"(__float_as_uint(b)));
    return r;
}
__device__ __forceinline__ void unpack2(unsigned long long v, float& a, float& b) {
    unsigned int lo, hi;
    asm("mov.b64 {%0, %1}, %2;" : "=r"(lo), "=r"(hi) : "l"(v));
    a = __uint_as_float(lo); b = __uint_as_float(hi);
}
__device__ __forceinline__ void ffma2(unsigned long long& d,
                                      unsigned long long a, unsigned long long b) {
    asm("fma.rn.f32x2 %0, %1, %2, %0;" : "+l"(d) : "l"(a), "l"(b));
}

// ---------------- 1. transpose x (C, vox) -> xt (vox, C) --------------------
__global__ void __launch_bounds__(256) transpose_kernel(const float* __restrict__ x) {
    __shared__ float s[32][33];
    int v0 = blockIdx.x * 32;
    int tx = threadIdx.x, ty = threadIdx.y;   // (32, 8)
#pragma unroll
    for (int i = 0; i < 4; i++) {
        int c = ty + 8 * i;
        s[c][tx] = x[c * NVOX + v0 + tx];     // coalesced over spatial
    }
    __syncthreads();
#pragma unroll
    for (int i = 0; i < 4; i++) {
        int vv = ty + 8 * i;
        g_xt[(size_t)(v0 + vv) * 32 + tx] = s[tx][vv];  // coalesced over channel
    }
}

// ---------------- 2. weight / bias reorg -------------------------------------
__global__ void reorg_kernel(const float* __restrict__ w_off,
                             const float* __restrict__ b_off,
                             const float* __restrict__ w_mask,
                             const float* __restrict__ b_mask,
                             const float* __restrict__ w) {
    int idx = blockIdx.x * 256 + threadIdx.x;
    if (idx < KK * CIN * OC108) {
        int oc  = idx % OC108;
        int cin = (idx / OC108) % CIN;
        int k   = idx / (OC108 * CIN);
        float val = (oc < 81) ? w_off[(oc * CIN + cin) * KK + k]
                              : w_mask[((oc - 81) * CIN + cin) * KK + k];
        g_wr[idx] = val;
    }
    if (idx < KK * CIN * COUT) {
        int o = idx & 31;
        int c = (idx >> 5) & 31;
        int k = idx >> 10;
        g_wcv[idx] = w[(o * CIN + c) * KK + k];
    }
    if (idx < OC108) {
        g_bias108[idx] = (idx < 81) ? b_off[idx] : b_mask[idx - 81];
    }
}

// ---------------- 3. fused 108-channel 3x3x3 conv + sigmoid -----------------
__global__ void __launch_bounds__(128) conv_offmask_kernel() {
    int v  = blockIdx.x * 128 + threadIdx.x;
    int xw = v & 63, y = (v >> 6) & 63, z = v >> 12;

    unsigned long long acc[54];
#pragma unroll
    for (int j = 0; j < 54; j++)
        acc[j] = pack2(g_bias108[2 * j], g_bias108[2 * j + 1]);

    for (int kz = 0; kz < 3; kz++) {
        int zz = z + kz - 1;
        if ((unsigned)zz >= (unsigned)DD) continue;
        for (int ky = 0; ky < 3; ky++) {
            int yy = y + ky - 1;
            if ((unsigned)yy >= (unsigned)HH) continue;
            for (int kx = 0; kx < 3; kx++) {
                int xx = xw + kx - 1;
                if ((unsigned)xx >= (unsigned)WW) continue;
                const float4* xp =
                    (const float4*)(g_xt + (((size_t)(zz * HH + yy) * WW + xx) << 5));
                int tap = kz * 9 + ky * 3 + kx;
                const ulonglong2* wp =
                    (const ulonglong2*)(g_wr + (size_t)(tap * CIN) * OC108);
                // wp rows: cin-th row starts at ull2 offset cin*27
#pragma unroll 1
                for (int c4 = 0; c4 < 8; c4++) {
                    float4 xv = __ldg(xp + c4);
                    float xs0 = xv.x, xs1 = xv.y, xs2 = xv.z, xs3 = xv.w;
#pragma unroll
                    for (int cc = 0; cc < 4; cc++) {
                        float xc = (cc == 0) ? xs0 : (cc == 1) ? xs1 : (cc == 2) ? xs2 : xs3;
                        unsigned long long x2 = pack2(xc, xc);
                        const ulonglong2* row = wp + (c4 * 4 + cc) * 27;
#pragma unroll
                        for (int j = 0; j < 27; j++) {
                            ulonglong2 wv = __ldg(row + j);
                            ffma2(acc[2 * j],     x2, wv.x);
                            ffma2(acc[2 * j + 1], x2, wv.y);
                        }
                    }
                }
            }
        }
    }

    float4* outp = (float4*)(g_offmask + (size_t)v * OC108);
#pragma unroll
    for (int j = 0; j < 27; j++) {
        float f[4];
        unpack2(acc[2 * j],     f[0], f[1]);
        unpack2(acc[2 * j + 1], f[2], f[3]);
#pragma unroll
        for (int e = 0; e < 4; e++) {
            if (4 * j + e >= 81) f[e] = 1.0f / (1.0f + __expf(-f[e]));
        }
        outp[j] = make_float4(f[0], f[1], f[2], f[3]);
    }
}

// ---------------- 4. trilinear deform sample + mask + contraction -----------
__global__ void __launch_bounds__(128) deform_kernel(const float* __restrict__ bfin,
                                                     float* __restrict__ out) {
    int v  = blockIdx.x * 128 + threadIdx.x;
    int xw = v & 63, y = (v >> 6) & 63, z = v >> 12;

    unsigned long long acc[16];
#pragma unroll
    for (int i = 0; i < 16; i++)
        acc[i] = pack2(__ldg(bfin + 2 * i), __ldg(bfin + 2 * i + 1));

    const float* om = g_offmask + (size_t)v * OC108;

#pragma unroll 1
    for (int k = 0; k < KK; k++) {
        int kz = k / 9, ky = (k / 3) % 3, kx = k % 3;
        float oz = __ldg(om + k);
        float oy = __ldg(om + 27 + k);
        float ox = __ldg(om + 54 + k);
        float m  = __ldg(om + 81 + k);

        float zc = (float)(z - 1 + kz) + oz;
        float yc = (float)(y - 1 + ky) + oy;
        float xc = (float)(xw - 1 + kx) + ox;

        float zf0 = floorf(zc), yf0 = floorf(yc), xf0 = floorf(xc);
        float fz = zc - zf0, fy = yc - yf0, fx = xc - xf0;
        int z0 = (int)zf0, y0 = (int)yf0, x0 = (int)xf0;

        float wz[2], wy[2], wx[2];
        int zi[2], yi[2], xi[2];
        wz[0] = (1.f - fz) * m; wz[1] = fz * m;   // fold mask into z-weights
        wy[0] = 1.f - fy;       wy[1] = fy;
        wx[0] = 1.f - fx;       wx[1] = fx;
#pragma unroll
        for (int d = 0; d < 2; d++) {
            int zz = z0 + d, yyi = y0 + d, xxi = x0 + d;
            if ((unsigned)zz  >= (unsigned)DD) wz[d] = 0.f;
            if ((unsigned)yyi >= (unsigned)HH) wy[d] = 0.f;
            if ((unsigned)xxi >= (unsigned)WW) wx[d] = 0.f;
            zi[d] = min(max(zz, 0), DD - 1);
            yi[d] = min(max(yyi, 0), HH - 1);
            xi[d] = min(max(xxi, 0), WW - 1);
        }

        unsigned long long s[16];
#pragma unroll
        for (int i = 0; i < 16; i++) s[i] = 0ull;

#pragma unroll
        for (int c = 0; c < 8; c++) {
            int dz = c >> 2, dy = (c >> 1) & 1, dx = c & 1;
            float wgt = wz[dz] * wy[dy] * wx[dx];
            unsigned long long w2 = pack2(wgt, wgt);
            const ulonglong2* gp =
                (const ulonglong2*)(g_xt +
                    (((size_t)(zi[dz] * HH + yi[dy]) * WW + xi[dx]) << 5));
#pragma unroll
            for (int q = 0; q < 8; q++) {
                ulonglong2 g = __ldg(gp + q);
                ffma2(s[2 * q],     w2, g.x);
                ffma2(s[2 * q + 1], w2, g.y);
            }
        }

        // contraction: acc[o] += s[cin] * wcv[k][cin][o]
        const ulonglong2* wp = (const ulonglong2*)(g_wcv + (size_t)k * CIN * COUT);
#pragma unroll
        for (int c2 = 0; c2 < 16; c2++) {
            float f0, f1;
            unpack2(s[c2], f0, f1);
            unsigned long long a0 = pack2(f0, f0);
            unsigned long long a1 = pack2(f1, f1);
            const ulonglong2* r0 = wp + (2 * c2) * 8;       // 32 floats per cin
            const ulonglong2* r1 = wp + (2 * c2 + 1) * 8;
#pragma unroll
            for (int q = 0; q < 8; q++) {
                ulonglong2 w0 = __ldg(r0 + q);
                ulonglong2 w1 = __ldg(r1 + q);
                ffma2(acc[2 * q],     a0, w0.x);
                ffma2(acc[2 * q + 1], a0, w0.y);
                ffma2(acc[2 * q],     a1, w1.x);
                ffma2(acc[2 * q + 1], a1, w1.y);
            }
        }
    }

    // store NCDHW: out[o][v], coalesced across lanes
#pragma unroll
    for (int i = 0; i < 16; i++) {
        float f0, f1;
        unpack2(acc[i], f0, f1);
        out[(2 * i) * NVOX + v]     = f0;
        out[(2 * i + 1) * NVOX + v] = f1;
    }
}

// ---------------------------------------------------------------------------
static const float* pick(void* const* d_in, const int* in_sizes, int n_in, int want) {
    for (int i = 0; i < n_in; i++)
        if (in_sizes[i] == want) return (const float*)d_in[i];
    return nullptr;
}

extern "C" void kernel_launch(void* const* d_in, const int* in_sizes, int n_in,
                              void* d_out, int out_size) {
    // identify inputs by element count (all distinct)
    const float* x      = pick(d_in, in_sizes, n_in, NVOX * CIN);        // 4194304
    const float* w_off  = pick(d_in, in_sizes, n_in, 81 * CIN * KK);     // 69984
    const float* b_off  = pick(d_in, in_sizes, n_in, 81);
    const float* w_mask = pick(d_in, in_sizes, n_in, 27 * CIN * KK);     // 23328
    const float* b_mask = pick(d_in, in_sizes, n_in, 27);
    const float* w      = pick(d_in, in_sizes, n_in, COUT * CIN * KK);   // 27648
    const float* b      = pick(d_in, in_sizes, n_in, COUT);              // 32
    float* out = (float*)d_out;

    transpose_kernel<<<NVOX / 32, dim3(32, 8)>>>(x);
    reorg_kernel<<<(KK * CIN * OC108 + 255) / 256, 256>>>(w_off, b_off, w_mask, b_mask, w);
    conv_offmask_kernel<<<NVOX / 128, 128>>>();
    deform_kernel<<<NVOX / 128, 128>>>(b, out);
}

// round 2
// speedup vs baseline: 1.4789x; 1.4789x over previous
#include <cuda_runtime.h>
#include <cuda_bf16.h>

// ---------------------------------------------------------------------------
// DeformableConv3D  (B=1, CIN=COUT=32, D=32, H=W=64, KS=3, stride=1, pad=1)
//
//  1. transpose x (C,D,H,W) -> xt (D,H,W,C)  channels-last
//  2. reorg weights: wrp[864][128] padded (off||mask||0), wcv[k][cin][oc]
//  3. conv as smem-tiled GEMM (128vox x 128oc, k=864), sigmoid fused
//  4. deform: 2 voxels/thread, trilinear gather + masked contraction
// ---------------------------------------------------------------------------

#define DD 32
#define HH 64
#define WW 64
#define NVOX (DD*HH*WW)        // 131072
#define CIN 32
#define COUT 32
#define KK 27
#define OC108 108
#define OCP 128                 // padded conv output channels
#define KTOT (KK*CIN)           // 864

typedef unsigned long long ull;

// scratch (device globals; no allocations allowed)
__device__ float g_xt[NVOX * CIN];                 // 16 MB channels-last x
__device__ float g_wrp[KTOT * OCP];                // padded conv weights [k][ocp]
__device__ float g_wcv[KK * CIN * COUT];           // deform weights [k][cin][oc]
__device__ float g_bias128[OCP];
__device__ float g_offmask[(size_t)NVOX * OC108];  // 56.6 MB

// ---------------- packed f32x2 helpers --------------------------------------
__device__ __forceinline__ ull pack2(float a, float b) {
    ull r;
    asm("mov.b64 %0, {%1, %2};"
        : "=l"(r) : "r"(__float_as_uint(a)), "r"(__float_as_uint(b)));
    return r;
}
__device__ __forceinline__ void unpack2(ull v, float& a, float& b) {
    unsigned int lo, hi;
    asm("mov.b64 {%0, %1}, %2;" : "=r"(lo), "=r"(hi) : "l"(v));
    a = __uint_as_float(lo); b = __uint_as_float(hi);
}
__device__ __forceinline__ void ffma2(ull& d, ull a, ull b) {
    asm("fma.rn.f32x2 %0, %1, %2, %0;" : "+l"(d) : "l"(a), "l"(b));
}

// ---------------- 1. transpose x (C, vox) -> xt (vox, C) --------------------
__global__ void __launch_bounds__(256) transpose_kernel(const float* __restrict__ x) {
    __shared__ float s[32][33];
    int v0 = blockIdx.x * 32;
    int tx = threadIdx.x, ty = threadIdx.y;   // (32, 8)
#pragma unroll
    for (int i = 0; i < 4; i++) {
        int c = ty + 8 * i;
        s[c][tx] = x[c * NVOX + v0 + tx];
    }
    __syncthreads();
#pragma unroll
    for (int i = 0; i < 4; i++) {
        int vv = ty + 8 * i;
        g_xt[(size_t)(v0 + vv) * 32 + tx] = s[tx][vv];
    }
}

// ---------------- 2. weight / bias reorg -------------------------------------
__global__ void reorg_kernel(const float* __restrict__ w_off,
                             const float* __restrict__ b_off,
                             const float* __restrict__ w_mask,
                             const float* __restrict__ b_mask,
                             const float* __restrict__ w) {
    int idx = blockIdx.x * 256 + threadIdx.x;
    if (idx < KTOT * OCP) {
        int oc  = idx & (OCP - 1);
        int k   = idx >> 7;          // tap*32 + cin
        int tap = k >> 5;
        int cin = k & 31;
        float val = 0.0f;
        if (oc < 81)        val = w_off [(oc * CIN + cin) * KK + tap];
        else if (oc < 108)  val = w_mask[((oc - 81) * CIN + cin) * KK + tap];
        g_wrp[idx] = val;
    }
    if (idx < KK * CIN * COUT) {
        int o = idx & 31;
        int c = (idx >> 5) & 31;
        int k = idx >> 10;
        g_wcv[idx] = w[(o * CIN + c) * KK + k];
    }
    if (idx < OCP) {
        g_bias128[idx] = (idx < 81) ? b_off[idx]
                      : (idx < 108) ? b_mask[idx - 81] : 0.0f;
    }
}

// ---------------- 3. conv as smem-tiled GEMM ---------------------------------
// block: 256 threads, tile 128 voxels x 128 oc, k streamed per tap (32 cin)
__global__ void __launch_bounds__(256) conv_gemm_kernel() {
    __shared__ float Xs[32][128];   // [cin][vox]
    __shared__ float Ws[32][128];   // [cin][oc]

    int v0 = blockIdx.x * 128;
    int z  = v0 >> 12;
    int y0 = (v0 >> 6) & 63;        // even; tile spans y0, y0+1
    int t  = threadIdx.x;

    int ow = t & 15;                // oc group  -> oc = ow*8 .. +7
    int vw = t >> 4;                // vox group -> vox = vw*8 .. +7

    // loader mapping
    int lv = t & 127;               // voxel within tile
    int lc = (t >> 7) * 16;         // cin base (0 or 16)
    int lx = lv & 63;
    int ldy = lv >> 6;              // 0/1

    ull acc[8][4];
    {
        float4 b0 = *(const float4*)(g_bias128 + ow * 8);
        float4 b1 = *(const float4*)(g_bias128 + ow * 8 + 4);
#pragma unroll
        for (int i = 0; i < 8; i++) {
            acc[i][0] = pack2(b0.x, b0.y);
            acc[i][1] = pack2(b0.z, b0.w);
            acc[i][2] = pack2(b1.x, b1.y);
            acc[i][3] = pack2(b1.z, b1.w);
        }
    }

    for (int tap = 0; tap < KK; tap++) {
        int kz = tap / 9, ky = (tap / 3) % 3, kx = tap % 3;

        // --- load W tile (32 cin x 128 oc) : 16 floats/thread, coalesced
        {
            const float4* src = (const float4*)(g_wrp + (size_t)(tap * 32) * OCP) + t * 4;
            float4* dst = (float4*)(&Ws[0][0]) + t * 4;
#pragma unroll
            for (int j = 0; j < 4; j++) dst[j] = __ldg(src + j);
        }

        // --- load X tile (32 cin x 128 vox), transposed, with boundary zeros
        {
            int zz = z + kz - 1;
            int yy = y0 + ldy + ky - 1;
            int xx = lx + kx - 1;
            bool valid = ((unsigned)zz < (unsigned)DD) &&
                         ((unsigned)yy < (unsigned)HH) &&
                         ((unsigned)xx < (unsigned)WW);
            const float4* xp = valid
                ? (const float4*)(g_xt + (((size_t)(zz * HH + yy) * WW + xx) << 5) + lc)
                : nullptr;
#pragma unroll
            for (int j = 0; j < 4; j++) {
                float4 xv = valid ? __ldg(xp + j) : make_float4(0.f, 0.f, 0.f, 0.f);
                Xs[lc + 4 * j + 0][lv] = xv.x;
                Xs[lc + 4 * j + 1][lv] = xv.y;
                Xs[lc + 4 * j + 2][lv] = xv.z;
                Xs[lc + 4 * j + 3][lv] = xv.w;
            }
        }
        __syncthreads();

        // --- compute 32 k-steps
        const float* xrow = &Xs[0][vw * 8];
        const float* wrow = &Ws[0][ow * 8];
#pragma unroll 8
        for (int c = 0; c < 32; c++) {
            float4 xa = *(const float4*)(xrow + c * 128);
            float4 xb = *(const float4*)(xrow + c * 128 + 4);
            ulonglong2 wv0 = *(const ulonglong2*)(wrow + c * 128);
            ulonglong2 wv1 = *(const ulonglong2*)(wrow + c * 128 + 4);
            ull xs[8];
            xs[0] = pack2(xa.x, xa.x); xs[1] = pack2(xa.y, xa.y);
            xs[2] = pack2(xa.z, xa.z); xs[3] = pack2(xa.w, xa.w);
            xs[4] = pack2(xb.x, xb.x); xs[5] = pack2(xb.y, xb.y);
            xs[6] = pack2(xb.z, xb.z); xs[7] = pack2(xb.w, xb.w);
#pragma unroll
            for (int i = 0; i < 8; i++) {
                ffma2(acc[i][0], xs[i], wv0.x);
                ffma2(acc[i][1], xs[i], wv0.y);
                ffma2(acc[i][2], xs[i], wv1.x);
                ffma2(acc[i][3], xs[i], wv1.y);
            }
        }
        __syncthreads();
    }

    // --- sigmoid + store (oc < 108 only)
    if (ow < 14) {
#pragma unroll
        for (int i = 0; i < 8; i++) {
            int v = v0 + vw * 8 + i;
            float f[8];
            unpack2(acc[i][0], f[0], f[1]);
            unpack2(acc[i][1], f[2], f[3]);
            unpack2(acc[i][2], f[4], f[5]);
            unpack2(acc[i][3], f[6], f[7]);
#pragma unroll
            for (int j = 0; j < 8; j++) {
                int ocd = ow * 8 + j;
                if (ocd >= 81) f[j] = 1.0f / (1.0f + __expf(-f[j]));
            }
            float* op = g_offmask + (size_t)v * OC108 + ow * 8;
            *(float4*)(op)     = make_float4(f[0], f[1], f[2], f[3]);
            if (ow < 13)
                *(float4*)(op + 4) = make_float4(f[4], f[5], f[6], f[7]);
        }
    }
}

// ---------------- 4. deform: trilinear sample one voxel into s[16] ----------
__device__ __forceinline__ void sample_voxel(int z, int y, int xw,
                                             const float* __restrict__ om, int k,
                                             ull s[16]) {
    int kz = k / 9, ky = (k / 3) % 3, kx = k % 3;
    float oz = __ldg(om + k);
    float oy = __ldg(om + 27 + k);
    float ox = __ldg(om + 54 + k);
    float m  = __ldg(om + 81 + k);

    float zc = (float)(z - 1 + kz) + oz;
    float yc = (float)(y - 1 + ky) + oy;
    float xc = (float)(xw - 1 + kx) + ox;

    float zf0 = floorf(zc), yf0 = floorf(yc), xf0 = floorf(xc);
    float fz = zc - zf0, fy = yc - yf0, fx = xc - xf0;
    int z0 = (int)zf0, y0 = (int)yf0, x0 = (int)xf0;

    float wz[2], wy[2], wx[2];
    int zi[2], yi[2], xi[2];
    wz[0] = (1.f - fz) * m; wz[1] = fz * m;
    wy[0] = 1.f - fy;       wy[1] = fy;
    wx[0] = 1.f - fx;       wx[1] = fx;
#pragma unroll
    for (int d = 0; d < 2; d++) {
        int zz = z0 + d, yyi = y0 + d, xxi = x0 + d;
        if ((unsigned)zz  >= (unsigned)DD) wz[d] = 0.f;
        if ((unsigned)yyi >= (unsigned)HH) wy[d] = 0.f;
        if ((unsigned)xxi >= (unsigned)WW) wx[d] = 0.f;
        zi[d] = min(max(zz, 0), DD - 1);
        yi[d] = min(max(yyi, 0), HH - 1);
        xi[d] = min(max(xxi, 0), WW - 1);
    }

#pragma unroll
    for (int i = 0; i < 16; i++) s[i] = 0ull;

#pragma unroll
    for (int c = 0; c < 8; c++) {
        int dz = c >> 2, dy = (c >> 1) & 1, dx = c & 1;
        float wgt = wz[dz] * wy[dy] * wx[dx];
        ull w2 = pack2(wgt, wgt);
        const ulonglong2* gp =
            (const ulonglong2*)(g_xt +
                (((size_t)(zi[dz] * HH + yi[dy]) * WW + xi[dx]) << 5));
#pragma unroll
        for (int q = 0; q < 8; q++) {
            ulonglong2 g = __ldg(gp + q);
            ffma2(s[2 * q],     w2, g.x);
            ffma2(s[2 * q + 1], w2, g.y);
        }
    }
}

// 2 voxels (y, y+1) per thread: halves contraction weight traffic, 2x ILP
__global__ void __launch_bounds__(128) deform2_kernel(const float* __restrict__ bfin,
                                                      float* __restrict__ out) {
    int u  = blockIdx.x * 128 + threadIdx.x;    // 0 .. NVOX/2-1
    int xw = u & 63;
    int yh = (u >> 6) & 31;
    int z  = u >> 11;
    int y  = yh * 2;
    int v0 = z * 4096 + y * 64 + xw;
    int v1 = v0 + 64;

    ull acc0[16], acc1[16];
#pragma unroll
    for (int i = 0; i < 16; i++) {
        ull b = pack2(__ldg(bfin + 2 * i), __ldg(bfin + 2 * i + 1));
        acc0[i] = b; acc1[i] = b;
    }

    const float* om0 = g_offmask + (size_t)v0 * OC108;
    const float* om1 = g_offmask + (size_t)v1 * OC108;

#pragma unroll 1
    for (int k = 0; k < KK; k++) {
        ull s0[16], s1[16];
        sample_voxel(z, y,     xw, om0, k, s0);
        sample_voxel(z, y + 1, xw, om1, k, s1);

        const ulonglong2* wp = (const ulonglong2*)(g_wcv + (size_t)k * CIN * COUT);
#pragma unroll 2
        for (int c2 = 0; c2 < 16; c2++) {
            float f0, f1, g0, g1;
            unpack2(s0[c2], f0, f1);
            unpack2(s1[c2], g0, g1);
            ull a0 = pack2(f0, f0), a1 = pack2(f1, f1);
            ull b0 = pack2(g0, g0), b1 = pack2(g1, g1);
            const ulonglong2* r0 = wp + (2 * c2) * 8;
            const ulonglong2* r1 = wp + (2 * c2 + 1) * 8;
#pragma unroll
            for (int q = 0; q < 8; q++) {
                ulonglong2 w0 = __ldg(r0 + q);
                ulonglong2 w1 = __ldg(r1 + q);
                ffma2(acc0[2 * q],     a0, w0.x);
                ffma2(acc0[2 * q + 1], a0, w0.y);
                ffma2(acc0[2 * q],     a1, w1.x);
                ffma2(acc0[2 * q + 1], a1, w1.y);
                ffma2(acc1[2 * q],     b0, w0.x);
                ffma2(acc1[2 * q + 1], b0, w0.y);
                ffma2(acc1[2 * q],     b1, w1.x);
                ffma2(acc1[2 * q + 1], b1, w1.y);
            }
        }
    }

#pragma unroll
    for (int i = 0; i < 16; i++) {
        float f0, f1, g0, g1;
        unpack2(acc0[i], f0, f1);
        unpack2(acc1[i], g0, g1);
        out[(2 * i) * NVOX + v0]     = f0;
        out[(2 * i + 1) * NVOX + v0] = f1;
        out[(2 * i) * NVOX + v1]     = g0;
        out[(2 * i + 1) * NVOX + v1] = g1;
    }
}

// ---------------------------------------------------------------------------
static const float* pick(void* const* d_in, const int* in_sizes, int n_in, int want) {
    for (int i = 0; i < n_in; i++)
        if (in_sizes[i] == want) return (const float*)d_in[i];
    return nullptr;
}

extern "C" void kernel_launch(void* const* d_in, const int* in_sizes, int n_in,
                              void* d_out, int out_size) {
    const float* x      = pick(d_in, in_sizes, n_in, NVOX * CIN);
    const float* w_off  = pick(d_in, in_sizes, n_in, 81 * CIN * KK);
    const float* b_off  = pick(d_in, in_sizes, n_in, 81);
    const float* w_mask = pick(d_in, in_sizes, n_in, 27 * CIN * KK);
    const float* b_mask = pick(d_in, in_sizes, n_in, 27);
    const float* w      = pick(d_in, in_sizes, n_in, COUT * CIN * KK);
    const float* b      = pick(d_in, in_sizes, n_in, COUT);
    float* out = (float*)d_out;

    transpose_kernel<<<NVOX / 32, dim3(32, 8)>>>(x);
    reorg_kernel<<<(KTOT * OCP + 255) / 256, 256>>>(w_off, b_off, w_mask, b_mask, w);
    conv_gemm_kernel<<<NVOX / 128, 256>>>();
    deform2_kernel<<<NVOX / 2 / 128, 128>>>(b, out);
}

// round 3
// speedup vs baseline: 2.6075x; 1.7632x over previous
#include <cuda_runtime.h>
#include <cuda_bf16.h>

// ---------------------------------------------------------------------------
// DeformableConv3D  (B=1, CIN=COUT=32, D=32, H=W=64, KS=3, stride=1, pad=1)
//
//  1. transpose x (C,D,H,W) -> xt (D,H,W,C)  channels-last
//  2. reorg weights: wrp[864][128] padded (off||mask||0), wcv[k][cin][oc]
//  3. conv as smem-tiled GEMM (128vox x 128oc, k=864), sigmoid fused
//  4. deform3: cooperative coalesced gathers (8 lanes/voxel) -> smem tile
//     -> per-tap contraction with smem-staged weights
// ---------------------------------------------------------------------------

#define DD 32
#define HH 64
#define WW 64
#define NVOX (DD*HH*WW)        // 131072
#define CIN 32
#define COUT 32
#define KK 27
#define OC108 108
#define OCP 128
#define KTOT (KK*CIN)           // 864
#define XSTRIDE 68              // floats per Xval row (272B, conflict-free)

typedef unsigned long long ull;

// scratch (device globals; no allocations allowed)
__device__ float g_xt[NVOX * CIN];                 // 16 MB channels-last x
__device__ float g_wrp[KTOT * OCP];                // padded conv weights
__device__ float g_wcv[KK * CIN * COUT];           // deform weights [k][cin][oc]
__device__ float g_bias128[OCP];
__device__ float g_offmask[(size_t)NVOX * OC108];  // 56.6 MB

// ---------------- packed f32x2 helpers --------------------------------------
__device__ __forceinline__ ull pack2(float a, float b) {
    ull r;
    asm("mov.b64 %0, {%1, %2};"
        : "=l"(r) : "r"(__float_as_uint(a)), "r"(__float_as_uint(b)));
    return r;
}
__device__ __forceinline__ void unpack2(ull v, float& a, float& b) {
    unsigned int lo, hi;
    asm("mov.b64 {%0, %1}, %2;" : "=r"(lo), "=r"(hi) : "l"(v));
    a = __uint_as_float(lo); b = __uint_as_float(hi);
}
__device__ __forceinline__ void ffma2(ull& d, ull a, ull b) {
    asm("fma.rn.f32x2 %0, %1, %2, %0;" : "+l"(d) : "l"(a), "l"(b));
}

// ---------------- 1. transpose x (C, vox) -> xt (vox, C) --------------------
__global__ void __launch_bounds__(256) transpose_kernel(const float* __restrict__ x) {
    __shared__ float s[32][33];
    int v0 = blockIdx.x * 32;
    int tx = threadIdx.x, ty = threadIdx.y;   // (32, 8)
#pragma unroll
    for (int i = 0; i < 4; i++) {
        int c = ty + 8 * i;
        s[c][tx] = x[c * NVOX + v0 + tx];
    }
    __syncthreads();
#pragma unroll
    for (int i = 0; i < 4; i++) {
        int vv = ty + 8 * i;
        g_xt[(size_t)(v0 + vv) * 32 + tx] = s[tx][vv];
    }
}

// ---------------- 2. weight / bias reorg -------------------------------------
__global__ void reorg_kernel(const float* __restrict__ w_off,
                             const float* __restrict__ b_off,
                             const float* __restrict__ w_mask,
                             const float* __restrict__ b_mask,
                             const float* __restrict__ w) {
    int idx = blockIdx.x * 256 + threadIdx.x;
    if (idx < KTOT * OCP) {
        int oc  = idx & (OCP - 1);
        int k   = idx >> 7;
        int tap = k >> 5;
        int cin = k & 31;
        float val = 0.0f;
        if (oc < 81)        val = w_off [(oc * CIN + cin) * KK + tap];
        else if (oc < 108)  val = w_mask[((oc - 81) * CIN + cin) * KK + tap];
        g_wrp[idx] = val;
    }
    if (idx < KK * CIN * COUT) {
        int o = idx & 31;
        int c = (idx >> 5) & 31;
        int k = idx >> 10;
        g_wcv[idx] = w[(o * CIN + c) * KK + k];
    }
    if (idx < OCP) {
        g_bias128[idx] = (idx < 81) ? b_off[idx]
                      : (idx < 108) ? b_mask[idx - 81] : 0.0f;
    }
}

// ---------------- 3. conv as smem-tiled GEMM ---------------------------------
__global__ void __launch_bounds__(256) conv_gemm_kernel() {
    __shared__ float Xs[32][128];
    __shared__ float Ws[32][128];

    int v0 = blockIdx.x * 128;
    int z  = v0 >> 12;
    int y0 = (v0 >> 6) & 63;
    int t  = threadIdx.x;

    int ow = t & 15;
    int vw = t >> 4;

    int lv = t & 127;
    int lc = (t >> 7) * 16;
    int lx = lv & 63;
    int ldy = lv >> 6;

    ull acc[8][4];
    {
        float4 b0 = *(const float4*)(g_bias128 + ow * 8);
        float4 b1 = *(const float4*)(g_bias128 + ow * 8 + 4);
#pragma unroll
        for (int i = 0; i < 8; i++) {
            acc[i][0] = pack2(b0.x, b0.y);
            acc[i][1] = pack2(b0.z, b0.w);
            acc[i][2] = pack2(b1.x, b1.y);
            acc[i][3] = pack2(b1.z, b1.w);
        }
    }

    for (int tap = 0; tap < KK; tap++) {
        int kz = tap / 9, ky = (tap / 3) % 3, kx = tap % 3;

        {
            const float4* src = (const float4*)(g_wrp + (size_t)(tap * 32) * OCP) + t * 4;
            float4* dst = (float4*)(&Ws[0][0]) + t * 4;
#pragma unroll
            for (int j = 0; j < 4; j++) dst[j] = __ldg(src + j);
        }

        {
            int zz = z + kz - 1;
            int yy = y0 + ldy + ky - 1;
            int xx = lx + kx - 1;
            bool valid = ((unsigned)zz < (unsigned)DD) &&
                         ((unsigned)yy < (unsigned)HH) &&
                         ((unsigned)xx < (unsigned)WW);
            const float4* xp = valid
                ? (const float4*)(g_xt + (((size_t)(zz * HH + yy) * WW + xx) << 5) + lc)
                : nullptr;
#pragma unroll
            for (int j = 0; j < 4; j++) {
                float4 xv = valid ? __ldg(xp + j) : make_float4(0.f, 0.f, 0.f, 0.f);
                Xs[lc + 4 * j + 0][lv] = xv.x;
                Xs[lc + 4 * j + 1][lv] = xv.y;
                Xs[lc + 4 * j + 2][lv] = xv.z;
                Xs[lc + 4 * j + 3][lv] = xv.w;
            }
        }
        __syncthreads();

        const float* xrow = &Xs[0][vw * 8];
        const float* wrow = &Ws[0][ow * 8];
#pragma unroll 8
        for (int c = 0; c < 32; c++) {
            float4 xa = *(const float4*)(xrow + c * 128);
            float4 xb = *(const float4*)(xrow + c * 128 + 4);
            ulonglong2 wv0 = *(const ulonglong2*)(wrow + c * 128);
            ulonglong2 wv1 = *(const ulonglong2*)(wrow + c * 128 + 4);
            ull xs[8];
            xs[0] = pack2(xa.x, xa.x); xs[1] = pack2(xa.y, xa.y);
            xs[2] = pack2(xa.z, xa.z); xs[3] = pack2(xa.w, xa.w);
            xs[4] = pack2(xb.x, xb.x); xs[5] = pack2(xb.y, xb.y);
            xs[6] = pack2(xb.z, xb.z); xs[7] = pack2(xb.w, xb.w);
#pragma unroll
            for (int i = 0; i < 8; i++) {
                ffma2(acc[i][0], xs[i], wv0.x);
                ffma2(acc[i][1], xs[i], wv0.y);
                ffma2(acc[i][2], xs[i], wv1.x);
                ffma2(acc[i][3], xs[i], wv1.y);
            }
        }
        __syncthreads();
    }

    if (ow < 14) {
#pragma unroll
        for (int i = 0; i < 8; i++) {
            int v = v0 + vw * 8 + i;
            float f[8];
            unpack2(acc[i][0], f[0], f[1]);
            unpack2(acc[i][1], f[2], f[3]);
            unpack2(acc[i][2], f[4], f[5]);
            unpack2(acc[i][3], f[6], f[7]);
#pragma unroll
            for (int j = 0; j < 8; j++) {
                int ocd = ow * 8 + j;
                if (ocd >= 81) f[j] = 1.0f / (1.0f + __expf(-f[j]));
            }
            float* op = g_offmask + (size_t)v * OC108 + ow * 8;
            *(float4*)(op)     = make_float4(f[0], f[1], f[2], f[3]);
            if (ow < 13)
                *(float4*)(op + 4) = make_float4(f[4], f[5], f[6], f[7]);
        }
    }
}

// ---------------- 4. deform3: coalesced cooperative gather + smem GEMM ------
// block = 128 threads, tile = 128 voxels (2 x-rows).
// sampling: 8 passes, slot = p*128+t -> (voxel = slot>>3, chquad = slot&7);
//   8 lanes per voxel, each lane gathers 16B (4ch) per corner -> per warp
//   LDG.128 covers 4 full 128B lines (4 wf, ideal).
// contraction: thread t owns voxel t, 32 oc accumulators, weights from smem.
__global__ void __launch_bounds__(128) deform3_kernel(const float* __restrict__ bfin,
                                                      float* __restrict__ out) {
    __shared__ float Xval[128 * XSTRIDE];  // 34.8 KB
    __shared__ float Wsm[CIN * COUT];      // 4 KB per-tap weights

    int t  = threadIdx.x;
    int v0 = blockIdx.x * 128;

    ull acc[16];
#pragma unroll
    for (int i = 0; i < 16; i++)
        acc[i] = pack2(__ldg(bfin + 2 * i), __ldg(bfin + 2 * i + 1));

#pragma unroll 1
    for (int kt = 0; kt < KK; kt++) {
        int kz = kt / 9, ky = (kt / 3) % 3, kx = kt % 3;

        // stage this tap's contraction weights (4KB) into smem
        {
            const float4* wsrc = (const float4*)(g_wcv + (size_t)kt * CIN * COUT);
            ((float4*)Wsm)[t]       = __ldg(wsrc + t);
            ((float4*)Wsm)[t + 128] = __ldg(wsrc + t + 128);
        }

        // cooperative sampling: 1024 lane-slots, 8 passes
#pragma unroll 2
        for (int p = 0; p < 8; p++) {
            int slot = p * 128 + t;
            int vl = slot >> 3;
            int c4 = slot & 7;
            int v  = v0 + vl;
            int xw = v & 63, y = (v >> 6) & 63, z = v >> 12;

            const float* om = g_offmask + (size_t)v * OC108;
            float oz = __ldg(om + kt);
            float oy = __ldg(om + 27 + kt);
            float ox = __ldg(om + 54 + kt);
            float m  = __ldg(om + 81 + kt);

            float zc = (float)(z - 1 + kz) + oz;
            float yc = (float)(y - 1 + ky) + oy;
            float xc = (float)(xw - 1 + kx) + ox;

            float zf0 = floorf(zc), yf0 = floorf(yc), xf0 = floorf(xc);
            float fz = zc - zf0, fy = yc - yf0, fx = xc - xf0;
            int z0 = (int)zf0, y0i = (int)yf0, x0 = (int)xf0;

            float wz[2], wy[2], wx[2];
            int zi[2], yi[2], xi[2];
            wz[0] = (1.f - fz) * m; wz[1] = fz * m;
            wy[0] = 1.f - fy;       wy[1] = fy;
            wx[0] = 1.f - fx;       wx[1] = fx;
#pragma unroll
            for (int d = 0; d < 2; d++) {
                int zz = z0 + d, yyi = y0i + d, xxi = x0 + d;
                if ((unsigned)zz  >= (unsigned)DD) wz[d] = 0.f;
                if ((unsigned)yyi >= (unsigned)HH) wy[d] = 0.f;
                if ((unsigned)xxi >= (unsigned)WW) wx[d] = 0.f;
                zi[d] = min(max(zz, 0), DD - 1);
                yi[d] = min(max(yyi, 0), HH - 1);
                xi[d] = min(max(xxi, 0), WW - 1);
            }

            ull s0 = 0ull, s1 = 0ull;
#pragma unroll
            for (int c = 0; c < 8; c++) {
                int dz = c >> 2, dy = (c >> 1) & 1, dx = c & 1;
                float wgt = wz[dz] * wy[dy] * wx[dx];
                ull w2 = pack2(wgt, wgt);
                const ulonglong2* gp = (const ulonglong2*)
                    (g_xt + (((size_t)(zi[dz] * HH + yi[dy]) * WW + xi[dx]) << 5) + c4 * 4);
                ulonglong2 g = __ldg(gp);
                ffma2(s0, w2, g.x);
                ffma2(s1, w2, g.y);
            }
            float f0, f1, f2, f3;
            unpack2(s0, f0, f1);
            unpack2(s1, f2, f3);
            *(float4*)(Xval + vl * XSTRIDE + c4 * 4) = make_float4(f0, f1, f2, f3);
        }
        __syncthreads();

        // contraction: thread t = voxel v0+t; x row from smem (conflict-free),
        // weights broadcast from smem
        {
            float xr[32];
#pragma unroll
            for (int q = 0; q < 8; q++)
                *(float4*)(xr + 4 * q) = *(const float4*)(Xval + t * XSTRIDE + q * 4);

#pragma unroll 8
            for (int c = 0; c < 32; c++) {
                ull x2 = pack2(xr[c], xr[c]);
                const ulonglong2* wr = (const ulonglong2*)(Wsm + c * 32);
#pragma unroll
                for (int q = 0; q < 8; q++) {
                    ulonglong2 wv = wr[q];
                    ffma2(acc[2 * q],     x2, wv.x);
                    ffma2(acc[2 * q + 1], x2, wv.y);
                }
            }
        }
        __syncthreads();
    }

    int v = v0 + t;
#pragma unroll
    for (int i = 0; i < 16; i++) {
        float f0, f1;
        unpack2(acc[i], f0, f1);
        out[(2 * i) * NVOX + v]     = f0;
        out[(2 * i + 1) * NVOX + v] = f1;
    }
}

// ---------------------------------------------------------------------------
static const float* pick(void* const* d_in, const int* in_sizes, int n_in, int want) {
    for (int i = 0; i < n_in; i++)
        if (in_sizes[i] == want) return (const float*)d_in[i];
    return nullptr;
}

extern "C" void kernel_launch(void* const* d_in, const int* in_sizes, int n_in,
                              void* d_out, int out_size) {
    const float* x      = pick(d_in, in_sizes, n_in, NVOX * CIN);
    const float* w_off  = pick(d_in, in_sizes, n_in, 81 * CIN * KK);
    const float* b_off  = pick(d_in, in_sizes, n_in, 81);
    const float* w_mask = pick(d_in, in_sizes, n_in, 27 * CIN * KK);
    const float* b_mask = pick(d_in, in_sizes, n_in, 27);
    const float* w      = pick(d_in, in_sizes, n_in, COUT * CIN * KK);
    const float* b      = pick(d_in, in_sizes, n_in, COUT);
    float* out = (float*)d_out;

    transpose_kernel<<<NVOX / 32, dim3(32, 8)>>>(x);
    reorg_kernel<<<(KTOT * OCP + 255) / 256, 256>>>(w_off, b_off, w_mask, b_mask, w);
    conv_gemm_kernel<<<NVOX / 128, 256>>>();
    deform3_kernel<<<NVOX / 128, 128>>>(b, out);
}

// round 5
// speedup vs baseline: 4.2677x; 1.6367x over previous
#include <cuda_runtime.h>
#include <cuda_bf16.h>
#include <cstdint>

// ---------------------------------------------------------------------------
// DeformableConv3D  (B=1, CIN=COUT=32, D=32, H=W=64, KS=3, stride=1, pad=1)
//
//  1. transpose x (C,D,H,W) -> xt (D,H,W,C)
//  2. reorg: conv weights -> split-bf16 B image g_wbf[27][64][136] (hi|lo k);
//            deform weights wcv[k][cin][oc]; bias128
//  3. conv as HMMA bf16 implicit GEMM (mma.sync m16n8k16, fp32 accum),
//     split precision: xhi*whi + xhi*wlo + xlo*whi
//  4. deform3: cooperative coalesced gathers -> smem -> f32x2 contraction
// ---------------------------------------------------------------------------

#define DD 32
#define HH 64
#define WW 64
#define NVOX (DD*HH*WW)
#define CIN 32
#define COUT 32
#define KK 27
#define OC108 108
#define OCP 128
#define XSTRIDE 68
#define AST 72          // A smem row stride (bf16)
#define BST 136         // B smem row stride (bf16)

typedef unsigned long long ull;

__device__ float g_xt[NVOX * CIN];                     // 16 MB channels-last x
__device__ __nv_bfloat16 g_wbf[KK * 64 * BST];         // B smem image per tap
__device__ float g_wcv[KK * CIN * COUT];
__device__ float g_bias128[OCP];
__device__ float g_offmask[(size_t)NVOX * OC108];      // 56.6 MB

// ---------------- packed f32x2 helpers --------------------------------------
__device__ __forceinline__ ull pack2(float a, float b) {
    ull r;
    asm("mov.b64 %0, {%1, %2};"
        : "=l"(r) : "r"(__float_as_uint(a)), "r"(__float_as_uint(b)));
    return r;
}
__device__ __forceinline__ void unpack2(ull v, float& a, float& b) {
    unsigned int lo, hi;
    asm("mov.b64 {%0, %1}, %2;" : "=r"(lo), "=r"(hi) : "l"(v));
    a = __uint_as_float(lo); b = __uint_as_float(hi);
}
__device__ __forceinline__ void ffma2(ull& d, ull a, ull b) {
    asm("fma.rn.f32x2 %0, %1, %2, %0;" : "+l"(d) : "l"(a), "l"(b));
}

// ---------------- mma helpers -------------------------------------------------
__device__ __forceinline__ uint32_t smem_u32(const void* p) {
    uint32_t a;
    asm("{ .reg .u64 t; cvta.to.shared.u64 t, %1; cvt.u32.u64 %0, t; }"
        : "=r"(a) : "l"(p));
    return a;
}
__device__ __forceinline__ void ldmA(uint32_t a[4], uint32_t addr) {
    asm volatile("ldmatrix.sync.aligned.m8n8.x4.shared.b16 {%0,%1,%2,%3}, [%4];"
        : "=r"(a[0]), "=r"(a[1]), "=r"(a[2]), "=r"(a[3]) : "r"(addr));
}
__device__ __forceinline__ void ldmB(uint32_t b[2], uint32_t addr) {
    asm volatile("ldmatrix.sync.aligned.m8n8.x2.trans.shared.b16 {%0,%1}, [%2];"
        : "=r"(b[0]), "=r"(b[1]) : "r"(addr));
}
__device__ __forceinline__ void mma16816(float c[4], const uint32_t a[4],
                                         const uint32_t b[2]) {
    asm volatile(
        "mma.sync.aligned.m16n8k16.row.col.f32.bf16.bf16.f32 "
        "{%0,%1,%2,%3}, {%4,%5,%6,%7}, {%8,%9}, {%0,%1,%2,%3};"
        : "+f"(c[0]), "+f"(c[1]), "+f"(c[2]), "+f"(c[3])
        : "r"(a[0]), "r"(a[1]), "r"(a[2]), "r"(a[3]), "r"(b[0]), "r"(b[1]));
}

// ---------------- 1. transpose ----------------------------------------------
__global__ void __launch_bounds__(256) transpose_kernel(const float* __restrict__ x) {
    __shared__ float s[32][33];
    int v0 = blockIdx.x * 32;
    int tx = threadIdx.x, ty = threadIdx.y;
#pragma unroll
    for (int i = 0; i < 4; i++) {
        int c = ty + 8 * i;
        s[c][tx] = x[c * NVOX + v0 + tx];
    }
    __syncthreads();
#pragma unroll
    for (int i = 0; i < 4; i++) {
        int vv = ty + 8 * i;
        g_xt[(size_t)(v0 + vv) * 32 + tx] = s[tx][vv];
    }
}

// ---------------- 2. weight / bias reorg -------------------------------------
__global__ void reorg_kernel(const float* __restrict__ w_off,
                             const float* __restrict__ b_off,
                             const float* __restrict__ w_mask,
                             const float* __restrict__ b_mask,
                             const float* __restrict__ w) {
    int idx = blockIdx.x * 256 + threadIdx.x;
    if (idx < KK * 64 * BST) {
        int tap = idx / (64 * BST);
        int rem = idx % (64 * BST);
        int r   = rem / BST;        // k row: 0-31 hi, 32-63 lo
        int n   = rem % BST;        // oc (128) + pad (8)
        float out = 0.0f;
        if (n < OCP) {
            int cin = r & 31;
            float wv = 0.0f;
            if (n < 81)        wv = w_off [(n * CIN + cin) * KK + tap];
            else if (n < 108)  wv = w_mask[((n - 81) * CIN + cin) * KK + tap];
            __nv_bfloat16 hi = __float2bfloat16(wv);
            out = (r < 32) ? __bfloat162float(hi) : (wv - __bfloat162float(hi));
        }
        g_wbf[idx] = __float2bfloat16(out);
    }
    if (idx < KK * CIN * COUT) {
        int o = idx & 31;
        int c = (idx >> 5) & 31;
        int k = idx >> 10;
        g_wcv[idx] = w[(o * CIN + c) * KK + k];
    }
    if (idx < OCP) {
        g_bias128[idx] = (idx < 81) ? b_off[idx]
                      : (idx < 108) ? b_mask[idx - 81] : 0.0f;
    }
}

// ---------------- 3. conv via HMMA bf16 split GEMM ---------------------------
// 256 threads, tile 128 vox x 128 oc, K = 27 taps x (32 hi + 32 lo)
__global__ void __launch_bounds__(256) conv_hmma_kernel() {
    __shared__ __align__(16) __nv_bfloat16 As[128 * AST];  // 18432 B
    __shared__ __align__(16) __nv_bfloat16 Bs[64 * BST];   // 17408 B

    int t = threadIdx.x;
    int wid = t >> 5, lane = t & 31;
    int warp_m = wid >> 2;          // 0-1  -> 64 voxels
    int warp_n = wid & 3;           // 0-3  -> 32 oc

    int v0 = blockIdx.x * 128;
    int z  = v0 >> 12;
    int y0 = (v0 >> 6) & 63;

    uint32_t as_b = smem_u32(As);
    uint32_t bs_b = smem_u32(Bs);

    // ldmatrix lane addressing
    int arow = lane & 15;
    int acol = (lane >> 4) << 3;
    uint32_t a_base = as_b + ((warp_m * 64 + arow) * AST + acol) * 2;
    uint32_t b_base = bs_b + (arow * BST + warp_n * 32) * 2;

    float c[4][4][4];
#pragma unroll
    for (int mt = 0; mt < 4; mt++)
#pragma unroll
        for (int nt = 0; nt < 4; nt++)
#pragma unroll
            for (int e = 0; e < 4; e++) c[mt][nt][e] = 0.0f;

#pragma unroll 1
    for (int tap = 0; tap < KK; tap++) {
        int kz = tap / 9, ky = (tap / 3) % 3, kx = tap % 3;

        // --- B tile: linear copy of pre-imaged weights (17408 B)
        {
            const float4* src = (const float4*)(g_wbf + (size_t)tap * 64 * BST);
            float4* dst = (float4*)Bs;
#pragma unroll
            for (int j = 0; j < 5; j++) {
                int idx = t + j * 256;
                if (idx < 64 * BST / 8) dst[idx] = __ldg(src + idx);
            }
        }
        // --- A tile: gather x with halo, split bf16 hi|lo
        {
            int zz = z + kz - 1;
            bool zok = (unsigned)zz < (unsigned)DD;
#pragma unroll
            for (int p = 0; p < 4; p++) {
                int slot = p * 256 + t;
                int vl = slot >> 3, c4 = slot & 7;
                int yy = y0 + (vl >> 6) + ky - 1;
                int xx = (vl & 63) + kx - 1;
                bool valid = zok && ((unsigned)yy < (unsigned)HH) &&
                             ((unsigned)xx < (unsigned)WW);
                float4 xv = valid
                    ? __ldg((const float4*)(g_xt +
                        (((size_t)(zz * HH + yy) * WW + xx) << 5)) + c4)
                    : make_float4(0.f, 0.f, 0.f, 0.f);
                __nv_bfloat16 h0 = __float2bfloat16(xv.x);
                __nv_bfloat16 h1 = __float2bfloat16(xv.y);
                __nv_bfloat16 h2 = __float2bfloat16(xv.z);
                __nv_bfloat16 h3 = __float2bfloat16(xv.w);
                uint32_t hp0 = (uint32_t)__bfloat16_as_ushort(h0) |
                               ((uint32_t)__bfloat16_as_ushort(h1) << 16);
                uint32_t hp1 = (uint32_t)__bfloat16_as_ushort(h2) |
                               ((uint32_t)__bfloat16_as_ushort(h3) << 16);
                __nv_bfloat16 l0 = __float2bfloat16(xv.x - __bfloat162float(h0));
                __nv_bfloat16 l1 = __float2bfloat16(xv.y - __bfloat162float(h1));
                __nv_bfloat16 l2 = __float2bfloat16(xv.z - __bfloat162float(h2));
                __nv_bfloat16 l3 = __float2bfloat16(xv.w - __bfloat162float(h3));
                uint32_t lp0 = (uint32_t)__bfloat16_as_ushort(l0) |
                               ((uint32_t)__bfloat16_as_ushort(l1) << 16);
                uint32_t lp1 = (uint32_t)__bfloat16_as_ushort(l2) |
                               ((uint32_t)__bfloat16_as_ushort(l3) << 16);
                *(uint2*)(As + vl * AST + c4 * 4)      = make_uint2(hp0, hp1);
                *(uint2*)(As + vl * AST + 32 + c4 * 4) = make_uint2(lp0, lp1);
            }
        }
        __syncthreads();

        // --- compute: 2 k-chunks x 3 split products
#pragma unroll
        for (int chunk = 0; chunk < 2; chunk++) {
            int kc = chunk * 16;
            uint32_t ah[4][4], al[4][4], bh[4][2], bl[4][2];
#pragma unroll
            for (int mt = 0; mt < 4; mt++)
                ldmA(ah[mt], a_base + (mt * 16 * AST + kc) * 2);
#pragma unroll
            for (int nt = 0; nt < 4; nt++)
                ldmB(bh[nt], b_base + (kc * BST + nt * 8) * 2);
#pragma unroll
            for (int mt = 0; mt < 4; mt++)
#pragma unroll
                for (int nt = 0; nt < 4; nt++)
                    mma16816(c[mt][nt], ah[mt], bh[nt]);        // hi*hi
#pragma unroll
            for (int nt = 0; nt < 4; nt++)
                ldmB(bl[nt], b_base + ((32 + kc) * BST + nt * 8) * 2);
#pragma unroll
            for (int mt = 0; mt < 4; mt++)
#pragma unroll
                for (int nt = 0; nt < 4; nt++)
                    mma16816(c[mt][nt], ah[mt], bl[nt]);        // hi*lo
#pragma unroll
            for (int mt = 0; mt < 4; mt++)
                ldmA(al[mt], a_base + (mt * 16 * AST + 32 + kc) * 2);
#pragma unroll
            for (int mt = 0; mt < 4; mt++)
#pragma unroll
                for (int nt = 0; nt < 4; nt++)
                    mma16816(c[mt][nt], al[mt], bh[nt]);        // lo*hi
        }
        __syncthreads();
    }

    // --- epilogue: bias + sigmoid(oc>=81), write g_offmask[v][oc]
    int gq = lane >> 2;             // 0-7  (row within 8)
    int qq = lane & 3;              // col pair
#pragma unroll
    for (int nt = 0; nt < 4; nt++) {
        int oc = warp_n * 32 + nt * 8 + qq * 2;
        if (oc >= OC108) continue;
        float b0 = g_bias128[oc], b1 = g_bias128[oc + 1];
#pragma unroll
        for (int mt = 0; mt < 4; mt++) {
            int r0 = v0 + warp_m * 64 + mt * 16 + gq;
            float f0 = c[mt][nt][0] + b0;
            float f1 = c[mt][nt][1] + b1;
            float f2 = c[mt][nt][2] + b0;
            float f3 = c[mt][nt][3] + b1;
            if (oc     >= 81) { f0 = 1.f/(1.f+__expf(-f0)); f2 = 1.f/(1.f+__expf(-f2)); }
            if (oc + 1 >= 81) { f1 = 1.f/(1.f+__expf(-f1)); f3 = 1.f/(1.f+__expf(-f3)); }
            *(float2*)(g_offmask + (size_t)r0 * OC108 + oc)       = make_float2(f0, f1);
            *(float2*)(g_offmask + (size_t)(r0 + 8) * OC108 + oc) = make_float2(f2, f3);
        }
    }
}

// ---------------- 4. deform3 (unchanged) --------------------------------------
__global__ void __launch_bounds__(128) deform3_kernel(const float* __restrict__ bfin,
                                                      float* __restrict__ out) {
    __shared__ float Xval[128 * XSTRIDE];
    __shared__ float Wsm[CIN * COUT];

    int t  = threadIdx.x;
    int v0 = blockIdx.x * 128;

    ull acc[16];
#pragma unroll
    for (int i = 0; i < 16; i++)
        acc[i] = pack2(__ldg(bfin + 2 * i), __ldg(bfin + 2 * i + 1));

#pragma unroll 1
    for (int kt = 0; kt < KK; kt++) {
        int kz = kt / 9, ky = (kt / 3) % 3, kx = kt % 3;
        {
            const float4* wsrc = (const float4*)(g_wcv + (size_t)kt * CIN * COUT);
            ((float4*)Wsm)[t]       = __ldg(wsrc + t);
            ((float4*)Wsm)[t + 128] = __ldg(wsrc + t + 128);
        }
#pragma unroll 2
        for (int p = 0; p < 8; p++) {
            int slot = p * 128 + t;
            int vl = slot >> 3;
            int c4 = slot & 7;
            int v  = v0 + vl;
            int xw = v & 63, y = (v >> 6) & 63, z = v >> 12;

            const float* om = g_offmask + (size_t)v * OC108;
            float oz = __ldg(om + kt);
            float oy = __ldg(om + 27 + kt);
            float ox = __ldg(om + 54 + kt);
            float m  = __ldg(om + 81 + kt);

            float zc = (float)(z - 1 + kz) + oz;
            float yc = (float)(y - 1 + ky) + oy;
            float xc = (float)(xw - 1 + kx) + ox;

            float zf0 = floorf(zc), yf0 = floorf(yc), xf0 = floorf(xc);
            float fz = zc - zf0, fy = yc - yf0, fx = xc - xf0;
            int z0 = (int)zf0, y0i = (int)yf0, x0 = (int)xf0;

            float wz[2], wy[2], wx[2];
            int zi[2], yi[2], xi[2];
            wz[0] = (1.f - fz) * m; wz[1] = fz * m;
            wy[0] = 1.f - fy;       wy[1] = fy;
            wx[0] = 1.f - fx;       wx[1] = fx;
#pragma unroll
            for (int d = 0; d < 2; d++) {
                int zz = z0 + d, yyi = y0i + d, xxi = x0 + d;
                if ((unsigned)zz  >= (unsigned)DD) wz[d] = 0.f;
                if ((unsigned)yyi >= (unsigned)HH) wy[d] = 0.f;
                if ((unsigned)xxi >= (unsigned)WW) wx[d] = 0.f;
                zi[d] = min(max(zz, 0), DD - 1);
                yi[d] = min(max(yyi, 0), HH - 1);
                xi[d] = min(max(xxi, 0), WW - 1);
            }

            ull s0 = 0ull, s1 = 0ull;
#pragma unroll
            for (int cc = 0; cc < 8; cc++) {
                int dz = cc >> 2, dy = (cc >> 1) & 1, dx = cc & 1;
                float wgt = wz[dz] * wy[dy] * wx[dx];
                ull w2 = pack2(wgt, wgt);
                const ulonglong2* gp = (const ulonglong2*)
                    (g_xt + (((size_t)(zi[dz] * HH + yi[dy]) * WW + xi[dx]) << 5) + c4 * 4);
                ulonglong2 g = __ldg(gp);
                ffma2(s0, w2, g.x);
                ffma2(s1, w2, g.y);
            }
            float f0, f1, f2, f3;
            unpack2(s0, f0, f1);
            unpack2(s1, f2, f3);
            *(float4*)(Xval + vl * XSTRIDE + c4 * 4) = make_float4(f0, f1, f2, f3);
        }
        __syncthreads();
        {
            float xr[32];
#pragma unroll
            for (int q = 0; q < 8; q++)
                *(float4*)(xr + 4 * q) = *(const float4*)(Xval + t * XSTRIDE + q * 4);

#pragma unroll 8
            for (int cc = 0; cc < 32; cc++) {
                ull x2 = pack2(xr[cc], xr[cc]);
                const ulonglong2* wr = (const ulonglong2*)(Wsm + cc * 32);
#pragma unroll
                for (int q = 0; q < 8; q++) {
                    ulonglong2 wv = wr[q];
                    ffma2(acc[2 * q],     x2, wv.x);
                    ffma2(acc[2 * q + 1], x2, wv.y);
                }
            }
        }
        __syncthreads();
    }

    int v = v0 + t;
#pragma unroll
    for (int i = 0; i < 16; i++) {
        float f0, f1;
        unpack2(acc[i], f0, f1);
        out[(2 * i) * NVOX + v]     = f0;
        out[(2 * i + 1) * NVOX + v] = f1;
    }
}

// ---------------------------------------------------------------------------
static const float* pick(void* const* d_in, const int* in_sizes, int n_in, int want) {
    for (int i = 0; i < n_in; i++)
        if (in_sizes[i] == want) return (const float*)d_in[i];
    return nullptr;
}

extern "C" void kernel_launch(void* const* d_in, const int* in_sizes, int n_in,
                              void* d_out, int out_size) {
    const float* x      = pick(d_in, in_sizes, n_in, NVOX * CIN);
    const float* w_off  = pick(d_in, in_sizes, n_in, 81 * CIN * KK);
    const float* b_off  = pick(d_in, in_sizes, n_in, 81);
    const float* w_mask = pick(d_in, in_sizes, n_in, 27 * CIN * KK);
    const float* b_mask = pick(d_in, in_sizes, n_in, 27);
    const float* w      = pick(d_in, in_sizes, n_in, COUT * CIN * KK);
    const float* b      = pick(d_in, in_sizes, n_in, COUT);
    float* out = (float*)d_out;

    transpose_kernel<<<NVOX / 32, dim3(32, 8)>>>(x);
    reorg_kernel<<<(KK * 64 * BST + 255) / 256, 256>>>(w_off, b_off, w_mask, b_mask, w);
    conv_hmma_kernel<<<NVOX / 128, 256>>>();
    deform3_kernel<<<NVOX / 128, 128>>>(b, out);
}

// round 6
// speedup vs baseline: 4.4901x; 1.0521x over previous
#include <cuda_runtime.h>
#include <cuda_bf16.h>
#include <cstdint>

// ---------------------------------------------------------------------------
// DeformableConv3D  (B=1, CIN=COUT=32, D=32, H=W=64, KS=3, stride=1, pad=1)
//
//  1. transpose x (C,D,H,W) -> xt (D,H,W,C)
//  2. reorg: conv weights -> split-bf16 B image; deform weights; bias
//  3. conv as HMMA bf16 split GEMM -> offmask stored TRANSPOSED [108][NVOX]
//  4. deform4: per-voxel weight/addr precompute (smem) -> cooperative
//     coalesced gathers -> f32x2 contraction with smem weights
// ---------------------------------------------------------------------------

#define DD 32
#define HH 64
#define WW 64
#define NVOX (DD*HH*WW)
#define CIN 32
#define COUT 32
#define KK 27
#define OC108 108
#define OCP 128
#define XSTRIDE 68
#define AST 72          // A smem row stride (bf16)
#define BST 136         // B smem row stride (bf16)

typedef unsigned long long ull;

__device__ float g_xt[NVOX * CIN];                     // 16 MB channels-last x
__device__ __nv_bfloat16 g_wbf[KK * 64 * BST];         // B smem image per tap
__device__ float g_wcv[KK * CIN * COUT];
__device__ float g_bias128[OCP];
__device__ float g_offmask[(size_t)OC108 * NVOX];      // TRANSPOSED [comp][vox]

// ---------------- packed f32x2 helpers --------------------------------------
__device__ __forceinline__ ull pack2(float a, float b) {
    ull r;
    asm("mov.b64 %0, {%1, %2};"
        : "=l"(r) : "r"(__float_as_uint(a)), "r"(__float_as_uint(b)));
    return r;
}
__device__ __forceinline__ void unpack2(ull v, float& a, float& b) {
    unsigned int lo, hi;
    asm("mov.b64 {%0, %1}, %2;" : "=r"(lo), "=r"(hi) : "l"(v));
    a = __uint_as_float(lo); b = __uint_as_float(hi);
}
__device__ __forceinline__ void ffma2(ull& d, ull a, ull b) {
    asm("fma.rn.f32x2 %0, %1, %2, %0;" : "+l"(d) : "l"(a), "l"(b));
}

// ---------------- mma helpers -------------------------------------------------
__device__ __forceinline__ uint32_t smem_u32(const void* p) {
    uint32_t a;
    asm("{ .reg .u64 t; cvta.to.shared.u64 t, %1; cvt.u32.u64 %0, t; }"
        : "=r"(a) : "l"(p));
    return a;
}
__device__ __forceinline__ void ldmA(uint32_t a[4], uint32_t addr) {
    asm volatile("ldmatrix.sync.aligned.m8n8.x4.shared.b16 {%0,%1,%2,%3}, [%4];"
        : "=r"(a[0]), "=r"(a[1]), "=r"(a[2]), "=r"(a[3]) : "r"(addr));
}
__device__ __forceinline__ void ldmB(uint32_t b[2], uint32_t addr) {
    asm volatile("ldmatrix.sync.aligned.m8n8.x2.trans.shared.b16 {%0,%1}, [%2];"
        : "=r"(b[0]), "=r"(b[1]) : "r"(addr));
}
__device__ __forceinline__ void mma16816(float c[4], const uint32_t a[4],
                                         const uint32_t b[2]) {
    asm volatile(
        "mma.sync.aligned.m16n8k16.row.col.f32.bf16.bf16.f32 "
        "{%0,%1,%2,%3}, {%4,%5,%6,%7}, {%8,%9}, {%0,%1,%2,%3};"
        : "+f"(c[0]), "+f"(c[1]), "+f"(c[2]), "+f"(c[3])
        : "r"(a[0]), "r"(a[1]), "r"(a[2]), "r"(a[3]), "r"(b[0]), "r"(b[1]));
}

// ---------------- 1. transpose ----------------------------------------------
__global__ void __launch_bounds__(256) transpose_kernel(const float* __restrict__ x) {
    __shared__ float s[32][33];
    int v0 = blockIdx.x * 32;
    int tx = threadIdx.x, ty = threadIdx.y;
#pragma unroll
    for (int i = 0; i < 4; i++) {
        int c = ty + 8 * i;
        s[c][tx] = x[c * NVOX + v0 + tx];
    }
    __syncthreads();
#pragma unroll
    for (int i = 0; i < 4; i++) {
        int vv = ty + 8 * i;
        g_xt[(size_t)(v0 + vv) * 32 + tx] = s[tx][vv];
    }
}

// ---------------- 2. weight / bias reorg -------------------------------------
__global__ void reorg_kernel(const float* __restrict__ w_off,
                             const float* __restrict__ b_off,
                             const float* __restrict__ w_mask,
                             const float* __restrict__ b_mask,
                             const float* __restrict__ w) {
    int idx = blockIdx.x * 256 + threadIdx.x;
    if (idx < KK * 64 * BST) {
        int tap = idx / (64 * BST);
        int rem = idx % (64 * BST);
        int r   = rem / BST;
        int n   = rem % BST;
        float out = 0.0f;
        if (n < OCP) {
            int cin = r & 31;
            float wv = 0.0f;
            if (n < 81)        wv = w_off [(n * CIN + cin) * KK + tap];
            else if (n < 108)  wv = w_mask[((n - 81) * CIN + cin) * KK + tap];
            __nv_bfloat16 hi = __float2bfloat16(wv);
            out = (r < 32) ? __bfloat162float(hi) : (wv - __bfloat162float(hi));
        }
        g_wbf[idx] = __float2bfloat16(out);
    }
    if (idx < KK * CIN * COUT) {
        int o = idx & 31;
        int c = (idx >> 5) & 31;
        int k = idx >> 10;
        g_wcv[idx] = w[(o * CIN + c) * KK + k];
    }
    if (idx < OCP) {
        g_bias128[idx] = (idx < 81) ? b_off[idx]
                      : (idx < 108) ? b_mask[idx - 81] : 0.0f;
    }
}

// ---------------- 3. conv via HMMA bf16 split GEMM ---------------------------
__global__ void __launch_bounds__(256) conv_hmma_kernel() {
    __shared__ __align__(16) __nv_bfloat16 As[128 * AST];
    __shared__ __align__(16) __nv_bfloat16 Bs[64 * BST];

    int t = threadIdx.x;
    int wid = t >> 5, lane = t & 31;
    int warp_m = wid >> 2;
    int warp_n = wid & 3;

    int v0 = blockIdx.x * 128;
    int z  = v0 >> 12;
    int y0 = (v0 >> 6) & 63;

    uint32_t as_b = smem_u32(As);
    uint32_t bs_b = smem_u32(Bs);

    int arow = lane & 15;
    int acol = (lane >> 4) << 3;
    uint32_t a_base = as_b + ((warp_m * 64 + arow) * AST + acol) * 2;
    uint32_t b_base = bs_b + (arow * BST + warp_n * 32) * 2;

    float c[4][4][4];
#pragma unroll
    for (int mt = 0; mt < 4; mt++)
#pragma unroll
        for (int nt = 0; nt < 4; nt++)
#pragma unroll
            for (int e = 0; e < 4; e++) c[mt][nt][e] = 0.0f;

#pragma unroll 1
    for (int tap = 0; tap < KK; tap++) {
        int kz = tap / 9, ky = (tap / 3) % 3, kx = tap % 3;
        {
            const float4* src = (const float4*)(g_wbf + (size_t)tap * 64 * BST);
            float4* dst = (float4*)Bs;
#pragma unroll
            for (int j = 0; j < 5; j++) {
                int idx = t + j * 256;
                if (idx < 64 * BST / 8) dst[idx] = __ldg(src + idx);
            }
        }
        {
            int zz = z + kz - 1;
            bool zok = (unsigned)zz < (unsigned)DD;
#pragma unroll
            for (int p = 0; p < 4; p++) {
                int slot = p * 256 + t;
                int vl = slot >> 3, c4 = slot & 7;
                int yy = y0 + (vl >> 6) + ky - 1;
                int xx = (vl & 63) + kx - 1;
                bool valid = zok && ((unsigned)yy < (unsigned)HH) &&
                             ((unsigned)xx < (unsigned)WW);
                float4 xv = valid
                    ? __ldg((const float4*)(g_xt +
                        (((size_t)(zz * HH + yy) * WW + xx) << 5)) + c4)
                    : make_float4(0.f, 0.f, 0.f, 0.f);
                __nv_bfloat16 h0 = __float2bfloat16(xv.x);
                __nv_bfloat16 h1 = __float2bfloat16(xv.y);
                __nv_bfloat16 h2 = __float2bfloat16(xv.z);
                __nv_bfloat16 h3 = __float2bfloat16(xv.w);
                uint32_t hp0 = (uint32_t)__bfloat16_as_ushort(h0) |
                               ((uint32_t)__bfloat16_as_ushort(h1) << 16);
                uint32_t hp1 = (uint32_t)__bfloat16_as_ushort(h2) |
                               ((uint32_t)__bfloat16_as_ushort(h3) << 16);
                __nv_bfloat16 l0 = __float2bfloat16(xv.x - __bfloat162float(h0));
                __nv_bfloat16 l1 = __float2bfloat16(xv.y - __bfloat162float(h1));
                __nv_bfloat16 l2 = __float2bfloat16(xv.z - __bfloat162float(h2));
                __nv_bfloat16 l3 = __float2bfloat16(xv.w - __bfloat162float(h3));
                uint32_t lp0 = (uint32_t)__bfloat16_as_ushort(l0) |
                               ((uint32_t)__bfloat16_as_ushort(l1) << 16);
                uint32_t lp1 = (uint32_t)__bfloat16_as_ushort(l2) |
                               ((uint32_t)__bfloat16_as_ushort(l3) << 16);
                *(uint2*)(As + vl * AST + c4 * 4)      = make_uint2(hp0, hp1);
                *(uint2*)(As + vl * AST + 32 + c4 * 4) = make_uint2(lp0, lp1);
            }
        }
        __syncthreads();

#pragma unroll
        for (int chunk = 0; chunk < 2; chunk++) {
            int kc = chunk * 16;
            uint32_t ah[4][4], al[4][4], bh[4][2], bl[4][2];
#pragma unroll
            for (int mt = 0; mt < 4; mt++)
                ldmA(ah[mt], a_base + (mt * 16 * AST + kc) * 2);
#pragma unroll
            for (int nt = 0; nt < 4; nt++)
                ldmB(bh[nt], b_base + (kc * BST + nt * 8) * 2);
#pragma unroll
            for (int mt = 0; mt < 4; mt++)
#pragma unroll
                for (int nt = 0; nt < 4; nt++)
                    mma16816(c[mt][nt], ah[mt], bh[nt]);
#pragma unroll
            for (int nt = 0; nt < 4; nt++)
                ldmB(bl[nt], b_base + ((32 + kc) * BST + nt * 8) * 2);
#pragma unroll
            for (int mt = 0; mt < 4; mt++)
#pragma unroll
                for (int nt = 0; nt < 4; nt++)
                    mma16816(c[mt][nt], ah[mt], bl[nt]);
#pragma unroll
            for (int mt = 0; mt < 4; mt++)
                ldmA(al[mt], a_base + (mt * 16 * AST + 32 + kc) * 2);
#pragma unroll
            for (int mt = 0; mt < 4; mt++)
#pragma unroll
                for (int nt = 0; nt < 4; nt++)
                    mma16816(c[mt][nt], al[mt], bh[nt]);
        }
        __syncthreads();
    }

    // epilogue: bias + sigmoid, TRANSPOSED store g_offmask[oc][v]
    int gq = lane >> 2;
    int qq = lane & 3;
#pragma unroll
    for (int nt = 0; nt < 4; nt++) {
        int oc = warp_n * 32 + nt * 8 + qq * 2;
        if (oc >= OC108) continue;
        float b0 = g_bias128[oc], b1 = g_bias128[oc + 1];
        float* r0p = g_offmask + (size_t)oc * NVOX;
        float* r1p = g_offmask + (size_t)(oc + 1) * NVOX;
#pragma unroll
        for (int mt = 0; mt < 4; mt++) {
            int r0 = v0 + warp_m * 64 + mt * 16 + gq;
            float f0 = c[mt][nt][0] + b0;
            float f1 = c[mt][nt][1] + b1;
            float f2 = c[mt][nt][2] + b0;
            float f3 = c[mt][nt][3] + b1;
            if (oc     >= 81) { f0 = 1.f/(1.f+__expf(-f0)); f2 = 1.f/(1.f+__expf(-f2)); }
            if (oc + 1 >= 81) { f1 = 1.f/(1.f+__expf(-f1)); f3 = 1.f/(1.f+__expf(-f3)); }
            r0p[r0]     = f0;
            r1p[r0]     = f1;
            r0p[r0 + 8] = f2;
            r1p[r0 + 8] = f3;
        }
    }
}

// ---------------- 4. deform4: precompute + coalesced gather + contraction ----
__global__ void __launch_bounds__(128) deform4_kernel(const float* __restrict__ bfin,
                                                      float* __restrict__ out) {
    __shared__ float Xval[128 * XSTRIDE];      // 34.8 KB
    __shared__ float Wsm[CIN * COUT];          // 4 KB
    __shared__ float    Wc[8][128];            // 4 KB corner weights
    __shared__ uint32_t Ac[8][128];            // 4 KB corner voxel indices

    int t  = threadIdx.x;
    int v0 = blockIdx.x * 128;
    int v  = v0 + t;
    int xw = v & 63, y = (v >> 6) & 63, z = v >> 12;

    ull acc[16];
#pragma unroll
    for (int i = 0; i < 16; i++)
        acc[i] = pack2(__ldg(bfin + 2 * i), __ldg(bfin + 2 * i + 1));

#pragma unroll 1
    for (int kt = 0; kt < KK; kt++) {
        int kz = kt / 9, ky = (kt / 3) % 3, kx = kt % 3;

        // stage contraction weights
        {
            const float4* wsrc = (const float4*)(g_wcv + (size_t)kt * CIN * COUT);
            ((float4*)Wsm)[t]       = __ldg(wsrc + t);
            ((float4*)Wsm)[t + 128] = __ldg(wsrc + t + 128);
        }

        // --- phase A: per-voxel precompute (coalesced offset loads)
        {
            float oz = __ldg(g_offmask + (size_t)kt        * NVOX + v);
            float oy = __ldg(g_offmask + (size_t)(27 + kt) * NVOX + v);
            float ox = __ldg(g_offmask + (size_t)(54 + kt) * NVOX + v);
            float m  = __ldg(g_offmask + (size_t)(81 + kt) * NVOX + v);

            float zc = (float)(z - 1 + kz) + oz;
            float yc = (float)(y - 1 + ky) + oy;
            float xc = (float)(xw - 1 + kx) + ox;

            float zf0 = floorf(zc), yf0 = floorf(yc), xf0 = floorf(xc);
            float fz = zc - zf0, fy = yc - yf0, fx = xc - xf0;
            int z0 = (int)zf0, y0i = (int)yf0, x0 = (int)xf0;

            float wz[2], wy[2], wx[2];
            int zi[2], yi[2], xi[2];
            wz[0] = (1.f - fz) * m; wz[1] = fz * m;
            wy[0] = 1.f - fy;       wy[1] = fy;
            wx[0] = 1.f - fx;       wx[1] = fx;
#pragma unroll
            for (int d = 0; d < 2; d++) {
                int zz = z0 + d, yyi = y0i + d, xxi = x0 + d;
                if ((unsigned)zz  >= (unsigned)DD) wz[d] = 0.f;
                if ((unsigned)yyi >= (unsigned)HH) wy[d] = 0.f;
                if ((unsigned)xxi >= (unsigned)WW) wx[d] = 0.f;
                zi[d] = min(max(zz, 0), DD - 1);
                yi[d] = min(max(yyi, 0), HH - 1);
                xi[d] = min(max(xxi, 0), WW - 1);
            }
#pragma unroll
            for (int cc = 0; cc < 8; cc++) {
                int dz = cc >> 2, dy = (cc >> 1) & 1, dx = cc & 1;
                Wc[cc][t] = wz[dz] * wy[dy] * wx[dx];
                Ac[cc][t] = (uint32_t)((zi[dz] * HH + yi[dy]) * WW + xi[dx]);
            }
        }
        __syncthreads();

        // --- phase B: cooperative sampling (8 lanes/voxel, 16B each)
#pragma unroll 2
        for (int p = 0; p < 8; p++) {
            int slot = p * 128 + t;
            int vl = slot >> 3;
            int c4 = slot & 7;

            ull s0 = 0ull, s1 = 0ull;
#pragma unroll
            for (int cc = 0; cc < 8; cc++) {
                float wgt = Wc[cc][vl];
                uint32_t a = Ac[cc][vl];
                ulonglong2 g = __ldg((const ulonglong2*)
                    (g_xt + ((size_t)a << 5) + c4 * 4));
                ull w2 = pack2(wgt, wgt);
                ffma2(s0, w2, g.x);
                ffma2(s1, w2, g.y);
            }
            float f0, f1, f2, f3;
            unpack2(s0, f0, f1);
            unpack2(s1, f2, f3);
            *(float4*)(Xval + vl * XSTRIDE + c4 * 4) = make_float4(f0, f1, f2, f3);
        }
        __syncthreads();

        // --- phase C: contraction
        {
            float xr[32];
#pragma unroll
            for (int q = 0; q < 8; q++)
                *(float4*)(xr + 4 * q) = *(const float4*)(Xval + t * XSTRIDE + q * 4);

#pragma unroll 8
            for (int cc = 0; cc < 32; cc++) {
                ull x2 = pack2(xr[cc], xr[cc]);
                const ulonglong2* wr = (const ulonglong2*)(Wsm + cc * 32);
#pragma unroll
                for (int q = 0; q < 8; q++) {
                    ulonglong2 wv = wr[q];
                    ffma2(acc[2 * q],     x2, wv.x);
                    ffma2(acc[2 * q + 1], x2, wv.y);
                }
            }
        }
        __syncthreads();
    }

#pragma unroll
    for (int i = 0; i < 16; i++) {
        float f0, f1;
        unpack2(acc[i], f0, f1);
        out[(2 * i) * NVOX + v]     = f0;
        out[(2 * i + 1) * NVOX + v] = f1;
    }
}

// ---------------------------------------------------------------------------
static const float* pick(void* const* d_in, const int* in_sizes, int n_in, int want) {
    for (int i = 0; i < n_in; i++)
        if (in_sizes[i] == want) return (const float*)d_in[i];
    return nullptr;
}

extern "C" void kernel_launch(void* const* d_in, const int* in_sizes, int n_in,
                              void* d_out, int out_size) {
    const float* x      = pick(d_in, in_sizes, n_in, NVOX * CIN);
    const float* w_off  = pick(d_in, in_sizes, n_in, 81 * CIN * KK);
    const float* b_off  = pick(d_in, in_sizes, n_in, 81);
    const float* w_mask = pick(d_in, in_sizes, n_in, 27 * CIN * KK);
    const float* b_mask = pick(d_in, in_sizes, n_in, 27);
    const float* w      = pick(d_in, in_sizes, n_in, COUT * CIN * KK);
    const float* b      = pick(d_in, in_sizes, n_in, COUT);
    float* out = (float*)d_out;

    transpose_kernel<<<NVOX / 32, dim3(32, 8)>>>(x);
    reorg_kernel<<<(KK * 64 * BST + 255) / 256, 256>>>(w_off, b_off, w_mask, b_mask, w);
    conv_hmma_kernel<<<NVOX / 128, 256>>>();
    deform4_kernel<<<NVOX / 128, 128>>>(b, out);
}

// round 7
// speedup vs baseline: 5.6581x; 1.2601x over previous
#include <cuda_runtime.h>
#include <cuda_bf16.h>
#include <cstdint>

// ---------------------------------------------------------------------------
// DeformableConv3D  (B=1, CIN=COUT=32, D=32, H=W=64, KS=3, stride=1, pad=1)
//
//  1. transpose x (C,D,H,W) -> xt (D,H,W,C)
//  2. reorg: conv weights -> split-bf16 B image; deform weights -> split-bf16
//     [27][64][40] image; bias
//  3. conv as HMMA bf16 split GEMM -> offmask TRANSPOSED [108][NVOX]
//  4. deform5: precompute -> coalesced gathers -> split-bf16 smem tile ->
//     HMMA contraction (fp32 accum across taps)
// ---------------------------------------------------------------------------

#define DD 32
#define HH 64
#define WW 64
#define NVOX (DD*HH*WW)
#define CIN 32
#define COUT 32
#define KK 27
#define OC108 108
#define OCP 128
#define AST 72          // A smem row stride (bf16)
#define BST 136         // conv B smem row stride (bf16)
#define WBS 40          // deform W image row stride (bf16)

typedef unsigned long long ull;

__device__ float g_xt[NVOX * CIN];                     // 16 MB channels-last x
__device__ __nv_bfloat16 g_wbf[KK * 64 * BST];         // conv B image per tap
__device__ __nv_bfloat16 g_wcb[KK * 64 * WBS];         // deform W image per tap
__device__ float g_bias128[OCP];
__device__ float g_offmask[(size_t)OC108 * NVOX];      // TRANSPOSED [comp][vox]

// ---------------- packed f32x2 helpers --------------------------------------
__device__ __forceinline__ ull pack2(float a, float b) {
    ull r;
    asm("mov.b64 %0, {%1, %2};"
        : "=l"(r) : "r"(__float_as_uint(a)), "r"(__float_as_uint(b)));
    return r;
}
__device__ __forceinline__ void unpack2(ull v, float& a, float& b) {
    unsigned int lo, hi;
    asm("mov.b64 {%0, %1}, %2;" : "=r"(lo), "=r"(hi) : "l"(v));
    a = __uint_as_float(lo); b = __uint_as_float(hi);
}
__device__ __forceinline__ void ffma2(ull& d, ull a, ull b) {
    asm("fma.rn.f32x2 %0, %1, %2, %0;" : "+l"(d) : "l"(a), "l"(b));
}

// ---------------- mma helpers -------------------------------------------------
__device__ __forceinline__ uint32_t smem_u32(const void* p) {
    uint32_t a;
    asm("{ .reg .u64 t; cvta.to.shared.u64 t, %1; cvt.u32.u64 %0, t; }"
        : "=r"(a) : "l"(p));
    return a;
}
__device__ __forceinline__ void ldmA(uint32_t a[4], uint32_t addr) {
    asm volatile("ldmatrix.sync.aligned.m8n8.x4.shared.b16 {%0,%1,%2,%3}, [%4];"
        : "=r"(a[0]), "=r"(a[1]), "=r"(a[2]), "=r"(a[3]) : "r"(addr));
}
__device__ __forceinline__ void ldmB(uint32_t b[2], uint32_t addr) {
    asm volatile("ldmatrix.sync.aligned.m8n8.x2.trans.shared.b16 {%0,%1}, [%2];"
        : "=r"(b[0]), "=r"(b[1]) : "r"(addr));
}
__device__ __forceinline__ void mma16816(float c[4], const uint32_t a[4],
                                         const uint32_t b[2]) {
    asm volatile(
        "mma.sync.aligned.m16n8k16.row.col.f32.bf16.bf16.f32 "
        "{%0,%1,%2,%3}, {%4,%5,%6,%7}, {%8,%9}, {%0,%1,%2,%3};"
        : "+f"(c[0]), "+f"(c[1]), "+f"(c[2]), "+f"(c[3])
        : "r"(a[0]), "r"(a[1]), "r"(a[2]), "r"(a[3]), "r"(b[0]), "r"(b[1]));
}
__device__ __forceinline__ void split_store(__nv_bfloat16* base, int row, int col,
                                            float4 xv) {
    __nv_bfloat16 h0 = __float2bfloat16(xv.x);
    __nv_bfloat16 h1 = __float2bfloat16(xv.y);
    __nv_bfloat16 h2 = __float2bfloat16(xv.z);
    __nv_bfloat16 h3 = __float2bfloat16(xv.w);
    uint32_t hp0 = (uint32_t)__bfloat16_as_ushort(h0) |
                   ((uint32_t)__bfloat16_as_ushort(h1) << 16);
    uint32_t hp1 = (uint32_t)__bfloat16_as_ushort(h2) |
                   ((uint32_t)__bfloat16_as_ushort(h3) << 16);
    __nv_bfloat16 l0 = __float2bfloat16(xv.x - __bfloat162float(h0));
    __nv_bfloat16 l1 = __float2bfloat16(xv.y - __bfloat162float(h1));
    __nv_bfloat16 l2 = __float2bfloat16(xv.z - __bfloat162float(h2));
    __nv_bfloat16 l3 = __float2bfloat16(xv.w - __bfloat162float(h3));
    uint32_t lp0 = (uint32_t)__bfloat16_as_ushort(l0) |
                   ((uint32_t)__bfloat16_as_ushort(l1) << 16);
    uint32_t lp1 = (uint32_t)__bfloat16_as_ushort(l2) |
                   ((uint32_t)__bfloat16_as_ushort(l3) << 16);
    *(uint2*)(base + row * AST + col)      = make_uint2(hp0, hp1);
    *(uint2*)(base + row * AST + 32 + col) = make_uint2(lp0, lp1);
}

// ---------------- 1. transpose ----------------------------------------------
__global__ void __launch_bounds__(256) transpose_kernel(const float* __restrict__ x) {
    __shared__ float s[32][33];
    int v0 = blockIdx.x * 32;
    int tx = threadIdx.x, ty = threadIdx.y;
#pragma unroll
    for (int i = 0; i < 4; i++) {
        int c = ty + 8 * i;
        s[c][tx] = x[c * NVOX + v0 + tx];
    }
    __syncthreads();
#pragma unroll
    for (int i = 0; i < 4; i++) {
        int vv = ty + 8 * i;
        g_xt[(size_t)(v0 + vv) * 32 + tx] = s[tx][vv];
    }
}

// ---------------- 2. weight / bias reorg -------------------------------------
__global__ void reorg_kernel(const float* __restrict__ w_off,
                             const float* __restrict__ b_off,
                             const float* __restrict__ w_mask,
                             const float* __restrict__ b_mask,
                             const float* __restrict__ w) {
    int idx = blockIdx.x * 256 + threadIdx.x;
    if (idx < KK * 64 * BST) {
        int tap = idx / (64 * BST);
        int rem = idx % (64 * BST);
        int r   = rem / BST;
        int n   = rem % BST;
        float out = 0.0f;
        if (n < OCP) {
            int cin = r & 31;
            float wv = 0.0f;
            if (n < 81)        wv = w_off [(n * CIN + cin) * KK + tap];
            else if (n < 108)  wv = w_mask[((n - 81) * CIN + cin) * KK + tap];
            __nv_bfloat16 hi = __float2bfloat16(wv);
            out = (r < 32) ? __bfloat162float(hi) : (wv - __bfloat162float(hi));
        }
        g_wbf[idx] = __float2bfloat16(out);
    }
    if (idx < KK * 64 * WBS) {
        int tap = idx / (64 * WBS);
        int rem = idx % (64 * WBS);
        int r   = rem / WBS;
        int n   = rem % WBS;
        float out = 0.0f;
        if (n < COUT) {
            int cin = r & 31;
            float wv = w[(n * CIN + cin) * KK + tap];
            __nv_bfloat16 hi = __float2bfloat16(wv);
            out = (r < 32) ? __bfloat162float(hi) : (wv - __bfloat162float(hi));
        }
        g_wcb[idx] = __float2bfloat16(out);
    }
    if (idx < OCP) {
        g_bias128[idx] = (idx < 81) ? b_off[idx]
                      : (idx < 108) ? b_mask[idx - 81] : 0.0f;
    }
}

// ---------------- 3. conv via HMMA bf16 split GEMM ---------------------------
__global__ void __launch_bounds__(256) conv_hmma_kernel() {
    __shared__ __align__(16) __nv_bfloat16 As[128 * AST];
    __shared__ __align__(16) __nv_bfloat16 Bs[64 * BST];

    int t = threadIdx.x;
    int wid = t >> 5, lane = t & 31;
    int warp_m = wid >> 2;
    int warp_n = wid & 3;

    int v0 = blockIdx.x * 128;
    int z  = v0 >> 12;
    int y0 = (v0 >> 6) & 63;

    uint32_t as_b = smem_u32(As);
    uint32_t bs_b = smem_u32(Bs);

    int arow = lane & 15;
    int acol = (lane >> 4) << 3;
    uint32_t a_base = as_b + ((warp_m * 64 + arow) * AST + acol) * 2;
    uint32_t b_base = bs_b + (arow * BST + warp_n * 32) * 2;

    float c[4][4][4];
#pragma unroll
    for (int mt = 0; mt < 4; mt++)
#pragma unroll
        for (int nt = 0; nt < 4; nt++)
#pragma unroll
            for (int e = 0; e < 4; e++) c[mt][nt][e] = 0.0f;

#pragma unroll 1
    for (int tap = 0; tap < KK; tap++) {
        int kz = tap / 9, ky = (tap / 3) % 3, kx = tap % 3;
        {
            const float4* src = (const float4*)(g_wbf + (size_t)tap * 64 * BST);
            float4* dst = (float4*)Bs;
#pragma unroll
            for (int j = 0; j < 5; j++) {
                int idx = t + j * 256;
                if (idx < 64 * BST / 8) dst[idx] = __ldg(src + idx);
            }
        }
        {
            int zz = z + kz - 1;
            bool zok = (unsigned)zz < (unsigned)DD;
#pragma unroll
            for (int p = 0; p < 4; p++) {
                int slot = p * 256 + t;
                int vl = slot >> 3, c4 = slot & 7;
                int yy = y0 + (vl >> 6) + ky - 1;
                int xx = (vl & 63) + kx - 1;
                bool valid = zok && ((unsigned)yy < (unsigned)HH) &&
                             ((unsigned)xx < (unsigned)WW);
                float4 xv = valid
                    ? __ldg((const float4*)(g_xt +
                        (((size_t)(zz * HH + yy) * WW + xx) << 5)) + c4)
                    : make_float4(0.f, 0.f, 0.f, 0.f);
                split_store(As, vl, c4 * 4, xv);
            }
        }
        __syncthreads();

#pragma unroll
        for (int chunk = 0; chunk < 2; chunk++) {
            int kc = chunk * 16;
            uint32_t ah[4][4], al[4][4], bh[4][2], bl[4][2];
#pragma unroll
            for (int mt = 0; mt < 4; mt++)
                ldmA(ah[mt], a_base + (mt * 16 * AST + kc) * 2);
#pragma unroll
            for (int nt = 0; nt < 4; nt++)
                ldmB(bh[nt], b_base + (kc * BST + nt * 8) * 2);
#pragma unroll
            for (int mt = 0; mt < 4; mt++)
#pragma unroll
                for (int nt = 0; nt < 4; nt++)
                    mma16816(c[mt][nt], ah[mt], bh[nt]);
#pragma unroll
            for (int nt = 0; nt < 4; nt++)
                ldmB(bl[nt], b_base + ((32 + kc) * BST + nt * 8) * 2);
#pragma unroll
            for (int mt = 0; mt < 4; mt++)
#pragma unroll
                for (int nt = 0; nt < 4; nt++)
                    mma16816(c[mt][nt], ah[mt], bl[nt]);
#pragma unroll
            for (int mt = 0; mt < 4; mt++)
                ldmA(al[mt], a_base + (mt * 16 * AST + 32 + kc) * 2);
#pragma unroll
            for (int mt = 0; mt < 4; mt++)
#pragma unroll
                for (int nt = 0; nt < 4; nt++)
                    mma16816(c[mt][nt], al[mt], bh[nt]);
        }
        __syncthreads();
    }

    int gq = lane >> 2;
    int qq = lane & 3;
#pragma unroll
    for (int nt = 0; nt < 4; nt++) {
        int oc = warp_n * 32 + nt * 8 + qq * 2;
        if (oc >= OC108) continue;
        float b0 = g_bias128[oc], b1 = g_bias128[oc + 1];
        float* r0p = g_offmask + (size_t)oc * NVOX;
        float* r1p = g_offmask + (size_t)(oc + 1) * NVOX;
#pragma unroll
        for (int mt = 0; mt < 4; mt++) {
            int r0 = v0 + warp_m * 64 + mt * 16 + gq;
            float f0 = c[mt][nt][0] + b0;
            float f1 = c[mt][nt][1] + b1;
            float f2 = c[mt][nt][2] + b0;
            float f3 = c[mt][nt][3] + b1;
            if (oc     >= 81) { f0 = 1.f/(1.f+__expf(-f0)); f2 = 1.f/(1.f+__expf(-f2)); }
            if (oc + 1 >= 81) { f1 = 1.f/(1.f+__expf(-f1)); f3 = 1.f/(1.f+__expf(-f3)); }
            r0p[r0]     = f0;
            r1p[r0]     = f1;
            r0p[r0 + 8] = f2;
            r1p[r0 + 8] = f3;
        }
    }
}

// ---------------- 4. deform5: gather -> split-bf16 -> HMMA contraction -------
__global__ void __launch_bounds__(128) deform5_kernel(const float* __restrict__ bfin,
                                                      float* __restrict__ out) {
    __shared__ __align__(16) __nv_bfloat16 As[128 * AST];   // 18432 B
    __shared__ __align__(16) __nv_bfloat16 Wb[64 * WBS];    // 5120 B
    __shared__ float    Wc[8][128];                          // 4 KB
    __shared__ uint32_t Ac[8][128];                          // 4 KB

    int t  = threadIdx.x;
    int wid = t >> 5, lane = t & 31;
    int v0 = blockIdx.x * 128;
    int v  = v0 + t;
    int xw = v & 63, y = (v >> 6) & 63, z = v >> 12;

    uint32_t as_b = smem_u32(As);
    uint32_t wb_b = smem_u32(Wb);
    int arow = lane & 15;
    int acol = (lane >> 4) << 3;
    uint32_t a_base = as_b + ((wid * 32 + arow) * AST + acol) * 2;
    uint32_t b_base = wb_b + (arow * WBS) * 2;

    float c2[2][4][4];
#pragma unroll
    for (int mt = 0; mt < 2; mt++)
#pragma unroll
        for (int nt = 0; nt < 4; nt++)
#pragma unroll
            for (int e = 0; e < 4; e++) c2[mt][nt][e] = 0.0f;

#pragma unroll 1
    for (int kt = 0; kt < KK; kt++) {
        int kz = kt / 9, ky = (kt / 3) % 3, kx = kt % 3;

        // stage this tap's split-bf16 contraction weights (5120 B)
        {
            const float4* src = (const float4*)(g_wcb + (size_t)kt * 64 * WBS);
            float4* dst = (float4*)Wb;
#pragma unroll
            for (int j = 0; j < 3; j++) {
                int idx = t + j * 128;
                if (idx < 64 * WBS / 8) dst[idx] = __ldg(src + idx);
            }
        }

        // --- phase A: per-voxel precompute (coalesced offset loads)
        {
            float oz = __ldg(g_offmask + (size_t)kt        * NVOX + v);
            float oy = __ldg(g_offmask + (size_t)(27 + kt) * NVOX + v);
            float ox = __ldg(g_offmask + (size_t)(54 + kt) * NVOX + v);
            float m  = __ldg(g_offmask + (size_t)(81 + kt) * NVOX + v);

            float zc = (float)(z - 1 + kz) + oz;
            float yc = (float)(y - 1 + ky) + oy;
            float xc = (float)(xw - 1 + kx) + ox;

            float zf0 = floorf(zc), yf0 = floorf(yc), xf0 = floorf(xc);
            float fz = zc - zf0, fy = yc - yf0, fx = xc - xf0;
            int z0 = (int)zf0, y0i = (int)yf0, x0 = (int)xf0;

            float wz[2], wy[2], wx[2];
            int zi[2], yi[2], xi[2];
            wz[0] = (1.f - fz) * m; wz[1] = fz * m;
            wy[0] = 1.f - fy;       wy[1] = fy;
            wx[0] = 1.f - fx;       wx[1] = fx;
#pragma unroll
            for (int d = 0; d < 2; d++) {
                int zz = z0 + d, yyi = y0i + d, xxi = x0 + d;
                if ((unsigned)zz  >= (unsigned)DD) wz[d] = 0.f;
                if ((unsigned)yyi >= (unsigned)HH) wy[d] = 0.f;
                if ((unsigned)xxi >= (unsigned)WW) wx[d] = 0.f;
                zi[d] = min(max(zz, 0), DD - 1);
                yi[d] = min(max(yyi, 0), HH - 1);
                xi[d] = min(max(xxi, 0), WW - 1);
            }
#pragma unroll
            for (int cc = 0; cc < 8; cc++) {
                int dz = cc >> 2, dy = (cc >> 1) & 1, dx = cc & 1;
                Wc[cc][t] = wz[dz] * wy[dy] * wx[dx];
                Ac[cc][t] = (uint32_t)((zi[dz] * HH + yi[dy]) * WW + xi[dx]);
            }
        }
        __syncthreads();

        // --- phase B: cooperative sampling -> split-bf16 store into As
#pragma unroll 2
        for (int p = 0; p < 8; p++) {
            int slot = p * 128 + t;
            int vl = slot >> 3;
            int c4 = slot & 7;

            ull s0 = 0ull, s1 = 0ull;
#pragma unroll
            for (int cc = 0; cc < 8; cc++) {
                float wgt = Wc[cc][vl];
                uint32_t a = Ac[cc][vl];
                ulonglong2 g = __ldg((const ulonglong2*)
                    (g_xt + ((size_t)a << 5) + c4 * 4));
                ull w2 = pack2(wgt, wgt);
                ffma2(s0, w2, g.x);
                ffma2(s1, w2, g.y);
            }
            float f0, f1, f2, f3;
            unpack2(s0, f0, f1);
            unpack2(s1, f2, f3);
            split_store(As, vl, c4 * 4, make_float4(f0, f1, f2, f3));
        }
        __syncthreads();

        // --- phase C: HMMA contraction (3 split products x 2 k-chunks)
#pragma unroll
        for (int pr = 0; pr < 3; pr++) {
            int aoff = (pr == 2) ? 32 : 0;
            int boff = (pr == 1) ? 32 : 0;
#pragma unroll
            for (int chunk = 0; chunk < 2; chunk++) {
                int kc = chunk * 16;
                uint32_t a[2][4], bb[4][2];
#pragma unroll
                for (int mt = 0; mt < 2; mt++)
                    ldmA(a[mt], a_base + (mt * 16 * AST + aoff + kc) * 2);
#pragma unroll
                for (int nt = 0; nt < 4; nt++)
                    ldmB(bb[nt], b_base + ((boff + kc) * WBS + nt * 8) * 2);
#pragma unroll
                for (int mt = 0; mt < 2; mt++)
#pragma unroll
                    for (int nt = 0; nt < 4; nt++)
                        mma16816(c2[mt][nt], a[mt], bb[nt]);
            }
        }
        __syncthreads();
    }

    // --- epilogue: + bias, store out[oc][v]
    int gq = lane >> 2;
    int qq = lane & 3;
#pragma unroll
    for (int nt = 0; nt < 4; nt++) {
        int oc = nt * 8 + qq * 2;
        float b0 = __ldg(bfin + oc), b1 = __ldg(bfin + oc + 1);
        float* r0p = out + (size_t)oc * NVOX;
        float* r1p = out + (size_t)(oc + 1) * NVOX;
#pragma unroll
        for (int mt = 0; mt < 2; mt++) {
            int vv = v0 + wid * 32 + mt * 16 + gq;
            r0p[vv]     = c2[mt][nt][0] + b0;
            r1p[vv]     = c2[mt][nt][1] + b1;
            r0p[vv + 8] = c2[mt][nt][2] + b0;
            r1p[vv + 8] = c2[mt][nt][3] + b1;
        }
    }
}

// ---------------------------------------------------------------------------
static const float* pick(void* const* d_in, const int* in_sizes, int n_in, int want) {
    for (int i = 0; i < n_in; i++)
        if (in_sizes[i] == want) return (const float*)d_in[i];
    return nullptr;
}

extern "C" void kernel_launch(void* const* d_in, const int* in_sizes, int n_in,
                              void* d_out, int out_size) {
    const float* x      = pick(d_in, in_sizes, n_in, NVOX * CIN);
    const float* w_off  = pick(d_in, in_sizes, n_in, 81 * CIN * KK);
    const float* b_off  = pick(d_in, in_sizes, n_in, 81);
    const float* w_mask = pick(d_in, in_sizes, n_in, 27 * CIN * KK);
    const float* b_mask = pick(d_in, in_sizes, n_in, 27);
    const float* w      = pick(d_in, in_sizes, n_in, COUT * CIN * KK);
    const float* b      = pick(d_in, in_sizes, n_in, COUT);
    float* out = (float*)d_out;

    transpose_kernel<<<NVOX / 32, dim3(32, 8)>>>(x);
    reorg_kernel<<<(KK * 64 * BST + 255) / 256, 256>>>(w_off, b_off, w_mask, b_mask, w);
    conv_hmma_kernel<<<NVOX / 128, 256>>>();
    deform5_kernel<<<NVOX / 128, 128>>>(b, out);
}